// round 12
// baseline (speedup 1.0000x reference)
#include <cuda_runtime.h>
#include <cuda_bf16.h>
#include <math.h>
#include <stdint.h>

// ---------------------------------------------------------------------------
// BitNet b1.58 MLP, exact-integer formulation on legacy bf16 HMMA.
// R10 -> R11: fragment double-buffering in both GEMM mainloops (issue the
// 6 LDSMs of step ks+1 while the MMAs of step ks execute). Everything else
// identical to R10 (64x32 warp tiles, 2 CTAs/SM, 3-stage cp.async, fused
// gate+up with silu exchange, register-resident actquant).
// Arithmetic unchanged: codes in [-128,127] / ternary weights exact in bf16,
// fp32 accumulation of ints < 2^24 exact => rel_err 5.449e-4 reproduced.
// ---------------------------------------------------------------------------

#define Dd 2048
#define Ff 8192
#define Mm 4096

#define ROWB 144                 // 64 bf16 = 128B data + 16B pad
#define STG  36864               // 256 rows * 144B per pipeline stage
#define GEMM_SMEM (3 * STG)      // 110592 -> 2 CTAs/SM

__device__ __align__(128) __nv_bfloat16 g_wgb[Ff * Dd];
__device__ __align__(128) __nv_bfloat16 g_wub[Ff * Dd];
__device__ __align__(128) __nv_bfloat16 g_wdb[Dd * Ff];
__device__ __align__(128) __nv_bfloat16 g_xb[Mm * Dd];
__device__ __align__(128) __nv_bfloat16 g_hb[(size_t)Mm * Ff];
__device__ __align__(128) float g_H[(size_t)Mm * Ff];
__device__ float  g_xdq[Mm];
__device__ float  g_hdq[Mm];
__device__ double g_wsum[3];
__device__ float  g_wdq[3];

// ------------------------------ utilities ----------------------------------

__device__ __forceinline__ uint32_t smem_u32(const void* p) {
    uint32_t a;
    asm("{ .reg .u64 t; cvta.to.shared.u64 t, %1; cvt.u32.u64 %0, t; }"
        : "=r"(a) : "l"(p));
    return a;
}
__device__ __forceinline__ void cp16(uint32_t dst, const void* src) {
    asm volatile("cp.async.cg.shared.global [%0], [%1], 16;"
                 :: "r"(dst), "l"(src) : "memory");
}
__device__ __forceinline__ void cp_commit() {
    asm volatile("cp.async.commit_group;" ::: "memory");
}
__device__ __forceinline__ void cp_wait1() {
    asm volatile("cp.async.wait_group 1;" ::: "memory");
}
__device__ __forceinline__ void ldsm4(uint32_t* r, uint32_t addr) {
    asm volatile("ldmatrix.sync.aligned.m8n8.x4.shared.b16 {%0,%1,%2,%3}, [%4];"
                 : "=r"(r[0]), "=r"(r[1]), "=r"(r[2]), "=r"(r[3]) : "r"(addr));
}
__device__ __forceinline__ void mma_bf16(float* c, const uint32_t* a, const uint32_t* b) {
    asm volatile(
        "mma.sync.aligned.m16n8k16.row.col.f32.bf16.bf16.f32 "
        "{%0,%1,%2,%3}, {%4,%5,%6,%7}, {%8,%9}, {%0,%1,%2,%3};"
        : "+f"(c[0]), "+f"(c[1]), "+f"(c[2]), "+f"(c[3])
        : "r"(a[0]), "r"(a[1]), "r"(a[2]), "r"(a[3]), "r"(b[0]), "r"(b[1]));
}

__device__ __forceinline__ double warpReduceSumD(double v) {
#pragma unroll
    for (int o = 16; o > 0; o >>= 1) v += __shfl_xor_sync(0xffffffffu, v, o);
    return v;
}
__device__ __forceinline__ float warpReduceMax(float v) {
#pragma unroll
    for (int o = 16; o > 0; o >>= 1) v = fmaxf(v, __shfl_xor_sync(0xffffffffu, v, o));
    return v;
}
__device__ __forceinline__ float silu_f(float g) {
    float sig;
    if (g >= 0.0f) {
        sig = 1.0f / (1.0f + expf(-g));
    } else {
        float e = expf(g);
        sig = e / (1.0f + e);
    }
    return g * sig;
}

// ---------------------------- small kernels --------------------------------

__global__ void zero_scalars_kernel() {
    if (threadIdx.x < 3) g_wsum[threadIdx.x] = 0.0;
}

__global__ void absum3_kernel(const float* __restrict__ W0, const float* __restrict__ W1,
                              const float* __restrict__ W2, int n4) {
    const float* W = (blockIdx.y == 0) ? W0 : (blockIdx.y == 1) ? W1 : W2;
    float s = 0.0f;
    const float4* W4 = (const float4*)W;
    for (int i = blockIdx.x * blockDim.x + threadIdx.x; i < n4;
         i += gridDim.x * blockDim.x) {
        float4 w = W4[i];
        s += (fabsf(w.x) + fabsf(w.y)) + (fabsf(w.z) + fabsf(w.w));
    }
    double d = warpReduceSumD((double)s);
    __shared__ double rs[8];
    int warp = threadIdx.x >> 5, lane = threadIdx.x & 31;
    if (lane == 0) rs[warp] = d;
    __syncthreads();
    if (threadIdx.x == 0) {
        double t = 0.0;
#pragma unroll
        for (int i = 0; i < 8; i++) t += rs[i];
        atomicAdd(&g_wsum[blockIdx.y], t);
    }
}

__global__ void wquant3_kernel(const float* __restrict__ W0, const float* __restrict__ W1,
                               const float* __restrict__ W2,
                               __nv_bfloat16* __restrict__ Q0,
                               __nv_bfloat16* __restrict__ Q1,
                               __nv_bfloat16* __restrict__ Q2,
                               int n4, double inv_n) {
    const int y = blockIdx.y;
    const float* W = (y == 0) ? W0 : (y == 1) ? W1 : W2;
    __nv_bfloat16* Q = (y == 0) ? Q0 : (y == 1) ? Q1 : Q2;
    float mean = fmaxf((float)(g_wsum[y] * inv_n), 1e-5f);
    float ws = 1.0f / mean;
    int i = blockIdx.x * blockDim.x + threadIdx.x;
    if (i < n4) {
        float4 w = ((const float4*)W)[i];
        float qx = rintf(fminf(fmaxf(w.x * ws, -1.0f), 1.0f));
        float qy = rintf(fminf(fmaxf(w.y * ws, -1.0f), 1.0f));
        float qz = rintf(fminf(fmaxf(w.z * ws, -1.0f), 1.0f));
        float qw = rintf(fminf(fmaxf(w.w * ws, -1.0f), 1.0f));
        __nv_bfloat162 lo = __nv_bfloat162(__float2bfloat16(qx), __float2bfloat16(qy));
        __nv_bfloat162 hi = __nv_bfloat162(__float2bfloat16(qz), __float2bfloat16(qw));
        uint2 pk;
        pk.x = *(uint32_t*)&lo;
        pk.y = *(uint32_t*)&hi;
        ((uint2*)Q)[i] = pk;
    }
    if (i == 0) g_wdq[y] = 1.0f / ws;
}

// warp-per-row rmsnorm+quant for D=2048 (row held in registers, no smem)
__global__ void __launch_bounds__(256) actquant_x_kernel(
        const float* __restrict__ A, __nv_bfloat16* __restrict__ Q,
        float* __restrict__ DQ) {
    const int lane = threadIdx.x & 31;
    const int row = blockIdx.x * 8 + (threadIdx.x >> 5);
    const float4* a4 = (const float4*)(A + (size_t)row * Dd);
    uint2* q2 = (uint2*)(Q + (size_t)row * Dd);

    float4 v[16];
    double ss = 0.0;
    float mx = 0.0f;
#pragma unroll
    for (int p = 0; p < 16; p++) {
        v[p] = a4[p * 32 + lane];
        float q = (v[p].x * v[p].x + v[p].y * v[p].y)
                + (v[p].z * v[p].z + v[p].w * v[p].w);
        ss += (double)q;
        mx = fmaxf(mx, fmaxf(fmaxf(fabsf(v[p].x), fabsf(v[p].y)),
                             fmaxf(fabsf(v[p].z), fabsf(v[p].w))));
    }
    ss = warpReduceSumD(ss);
    mx = warpReduceMax(mx);
    float mean = (float)(ss / (double)Dd);
    float c = rsqrtf(mean + 1e-6f);
    float m = fmaxf(c * mx, 1e-5f);
    float scale = 127.0f / m;
    if (lane == 0) DQ[row] = 1.0f / scale;
#pragma unroll
    for (int p = 0; p < 16; p++) {
        float c0 = rintf(fminf(fmaxf((c * v[p].x) * scale, -128.0f), 127.0f));
        float c1 = rintf(fminf(fmaxf((c * v[p].y) * scale, -128.0f), 127.0f));
        float c2 = rintf(fminf(fmaxf((c * v[p].z) * scale, -128.0f), 127.0f));
        float c3 = rintf(fminf(fmaxf((c * v[p].w) * scale, -128.0f), 127.0f));
        __nv_bfloat162 lo = __nv_bfloat162(__float2bfloat16(c0), __float2bfloat16(c1));
        __nv_bfloat162 hi = __nv_bfloat162(__float2bfloat16(c2), __float2bfloat16(c3));
        uint2 pk;
        pk.x = *(uint32_t*)&lo;
        pk.y = *(uint32_t*)&hi;
        q2[p * 32 + lane] = pk;
    }
}

// block-per-row rmsnorm+quant for F=8192 (32 floats/thread in registers)
__global__ void __launch_bounds__(256) actquant_h_kernel(
        const float* __restrict__ A, __nv_bfloat16* __restrict__ Q,
        float* __restrict__ DQ) {
    __shared__ double rs[8];
    __shared__ float rm[8];
    __shared__ float s_c, s_scale;
    const int tid = threadIdx.x;
    const int row = blockIdx.x;
    const float4* a4 = (const float4*)(A + (size_t)row * Ff);
    uint2* q2 = (uint2*)(Q + (size_t)row * Ff);

    float4 v[8];
    double ss = 0.0;
    float mx = 0.0f;
#pragma unroll
    for (int p = 0; p < 8; p++) {
        v[p] = a4[p * 256 + tid];
        float q = (v[p].x * v[p].x + v[p].y * v[p].y)
                + (v[p].z * v[p].z + v[p].w * v[p].w);
        ss += (double)q;
        mx = fmaxf(mx, fmaxf(fmaxf(fabsf(v[p].x), fabsf(v[p].y)),
                             fmaxf(fabsf(v[p].z), fabsf(v[p].w))));
    }
    ss = warpReduceSumD(ss);
    mx = warpReduceMax(mx);
    int warp = tid >> 5, lane = tid & 31;
    if (lane == 0) { rs[warp] = ss; rm[warp] = mx; }
    __syncthreads();
    if (tid == 0) {
        double S = 0.0;
        float Mx = 0.0f;
#pragma unroll
        for (int i = 0; i < 8; i++) { S += rs[i]; Mx = fmaxf(Mx, rm[i]); }
        float mean = (float)(S / (double)Ff);
        float c = rsqrtf(mean + 1e-6f);
        float m = fmaxf(c * Mx, 1e-5f);
        float scale = 127.0f / m;
        s_c = c; s_scale = scale;
        DQ[row] = 1.0f / scale;
    }
    __syncthreads();
    const float c = s_c, scale = s_scale;
#pragma unroll
    for (int p = 0; p < 8; p++) {
        float c0 = rintf(fminf(fmaxf((c * v[p].x) * scale, -128.0f), 127.0f));
        float c1 = rintf(fminf(fmaxf((c * v[p].y) * scale, -128.0f), 127.0f));
        float c2 = rintf(fminf(fmaxf((c * v[p].z) * scale, -128.0f), 127.0f));
        float c3 = rintf(fminf(fmaxf((c * v[p].w) * scale, -128.0f), 127.0f));
        __nv_bfloat162 lo = __nv_bfloat162(__float2bfloat16(c0), __float2bfloat16(c1));
        __nv_bfloat162 hi = __nv_bfloat162(__float2bfloat16(c2), __float2bfloat16(c3));
        uint2 pk;
        pk.x = *(uint32_t*)&lo;
        pk.y = *(uint32_t*)&hi;
        q2[p * 256 + tid] = pk;
    }
}

// --------------------- fused gate+up bf16 HMMA GEMM ------------------------
// Block computes a 128x64 tile of BOTH gate and up (shared A tile).
// Warps 0-3: gate, warps 4-7: up; warp tile 64x32 (2 CTAs/SM).
// Mainloop: fragment double-buffering (LDSMs of ks+1 overlap MMAs of ks).
// Epilogue: gate warps stage silu(g) in smem; up warps multiply, write H.

__global__ void __launch_bounds__(256, 2) gateup_kernel(
        const __nv_bfloat16* __restrict__ Aq,
        const __nv_bfloat16* __restrict__ Bg,
        const __nv_bfloat16* __restrict__ Bu,
        float* __restrict__ H,
        const float* __restrict__ adq) {
    extern __shared__ __align__(128) char smem[];
    const uint32_t sbase = smem_u32(smem);
    const int tid = threadIdx.x;
    const int lane = tid & 31;
    const int g = lane >> 2, tig = lane & 3;
    const int w = tid >> 5;
    const int uw = w & 3;
    const int isUp = w >> 2;
    const int wmb = (uw >> 1) * 64;
    const int wnb = (uw & 1) * 32;
    const int bm = blockIdx.y * 128, bn = blockIdx.x * 64;
    const size_t Kb = (size_t)Dd * 2;

    float acc[4][4][4];
#pragma unroll
    for (int mt = 0; mt < 4; mt++)
#pragma unroll
        for (int nt = 0; nt < 4; nt++)
#pragma unroll
            for (int k = 0; k < 4; k++) acc[mt][nt][k] = 0.0f;

    auto LOAD = [&](int kc, int s) {
        uint32_t sa = sbase + s * STG;
        const size_t kof = (size_t)kc * 128;
        const char* Ag = (const char*)Aq + (size_t)bm * Kb + kof;
        const char* Gg = (const char*)Bg + (size_t)bn * Kb + kof;
        const char* Ug = (const char*)Bu + (size_t)bn * Kb + kof;
#pragma unroll
        for (int i = 0; i < 4; i++) {
            int idx = i * 256 + tid;
            int row = idx >> 3, ch = (idx & 7) * 16;
            cp16(sa + row * ROWB + ch, Ag + (size_t)row * Kb + ch);
        }
#pragma unroll
        for (int i = 0; i < 2; i++) {
            int idx = i * 256 + tid;
            int row = idx >> 3, ch = (idx & 7) * 16;
            cp16(sa + 18432 + row * ROWB + ch, Gg + (size_t)row * Kb + ch);
        }
#pragma unroll
        for (int i = 0; i < 2; i++) {
            int idx = i * 256 + tid;
            int row = idx >> 3, ch = (idx & 7) * 16;
            cp16(sa + 27648 + row * ROWB + ch, Ug + (size_t)row * Kb + ch);
        }
        cp_commit();
    };

    const int NK = Dd / 64;   // 32
    LOAD(0, 0); LOAD(1, 1);

    const uint32_t a_row = (uint32_t)(lane & 15);
    const uint32_t a_k   = (uint32_t)((lane >> 4) * 16);
    const uint32_t b_row = (uint32_t)(((lane >> 4) << 3) + (lane & 7));
    const uint32_t b_k   = (uint32_t)(((lane >> 3) & 1) * 16);

    uint32_t af[2][4][4], bf[2][4][2];

    int cs = 0;
    for (int kc = 0; kc < NK; kc++) {
        cp_wait1();
        __syncthreads();
        int ls = cs + 2; if (ls >= 3) ls -= 3;
        if (kc + 2 < NK) LOAD(kc + 2, ls); else cp_commit();

        const uint32_t sa = sbase + cs * STG;
        const uint32_t sbW = sa + 18432 + (uint32_t)isUp * 9216;

        // preload fragments for ks=0
#pragma unroll
        for (int mt = 0; mt < 4; mt++)
            ldsm4(af[0][mt], sa + (uint32_t)(wmb + mt * 16 + a_row) * ROWB + a_k);
#pragma unroll
        for (int p = 0; p < 2; p++) {
            uint32_t t[4];
            ldsm4(t, sbW + (uint32_t)(wnb + p * 16 + b_row) * ROWB + b_k);
            bf[0][2 * p][0] = t[0]; bf[0][2 * p][1] = t[1];
            bf[0][2 * p + 1][0] = t[2]; bf[0][2 * p + 1][1] = t[3];
        }

#pragma unroll
        for (int ks = 0; ks < 4; ks++) {
            const int cur = ks & 1, nxt = cur ^ 1;
            if (ks < 3) {
#pragma unroll
                for (int mt = 0; mt < 4; mt++)
                    ldsm4(af[nxt][mt], sa + (uint32_t)(wmb + mt * 16 + a_row) * ROWB
                                       + (uint32_t)((ks + 1) * 32) + a_k);
#pragma unroll
                for (int p = 0; p < 2; p++) {
                    uint32_t t[4];
                    ldsm4(t, sbW + (uint32_t)(wnb + p * 16 + b_row) * ROWB
                             + (uint32_t)((ks + 1) * 32) + b_k);
                    bf[nxt][2 * p][0] = t[0]; bf[nxt][2 * p][1] = t[1];
                    bf[nxt][2 * p + 1][0] = t[2]; bf[nxt][2 * p + 1][1] = t[3];
                }
            }
#pragma unroll
            for (int mt = 0; mt < 4; mt++)
#pragma unroll
                for (int nt = 0; nt < 4; nt++)
                    mma_bf16(acc[mt][nt], af[cur][mt], bf[cur][nt]);
        }
        cs++; if (cs == 3) cs = 0;
    }

    // ---- epilogue: exchange silu(g) via smem, write H = silu(g)*u ----
    __syncthreads();
    float* hstage = (float*)smem;    // [128][68]
    if (!isUp) {
        const float wgs = g_wdq[0];
#pragma unroll
        for (int mt = 0; mt < 4; mt++) {
            int r0 = wmb + mt * 16 + g;
            float s0 = adq[bm + r0] * wgs;
            float s1 = adq[bm + r0 + 8] * wgs;
#pragma unroll
            for (int nt = 0; nt < 4; nt++) {
                int c = wnb + nt * 8 + tig * 2;
                hstage[r0 * 68 + c]           = silu_f(acc[mt][nt][0] * s0);
                hstage[r0 * 68 + c + 1]       = silu_f(acc[mt][nt][1] * s0);
                hstage[(r0 + 8) * 68 + c]     = silu_f(acc[mt][nt][2] * s1);
                hstage[(r0 + 8) * 68 + c + 1] = silu_f(acc[mt][nt][3] * s1);
            }
        }
    }
    __syncthreads();
    if (isUp) {
        const float wus = g_wdq[1];
#pragma unroll
        for (int mt = 0; mt < 4; mt++) {
            int r0 = wmb + mt * 16 + g;
            float s0 = adq[bm + r0] * wus;
            float s1 = adq[bm + r0 + 8] * wus;
#pragma unroll
            for (int nt = 0; nt < 4; nt++) {
                int c = wnb + nt * 8 + tig * 2;
                float v00 = acc[mt][nt][0] * s0 * hstage[r0 * 68 + c];
                float v01 = acc[mt][nt][1] * s0 * hstage[r0 * 68 + c + 1];
                float v10 = acc[mt][nt][2] * s1 * hstage[(r0 + 8) * 68 + c];
                float v11 = acc[mt][nt][3] * s1 * hstage[(r0 + 8) * 68 + c + 1];
                *(float2*)&H[(size_t)(bm + r0) * Ff + bn + c] = make_float2(v00, v01);
                *(float2*)&H[(size_t)(bm + r0 + 8) * Ff + bn + c] = make_float2(v10, v11);
            }
        }
    }
}

// --------------------------- down bf16 HMMA GEMM ---------------------------
// Block 128x128, 8 warps (2x4), warp tile 64x32, fragment double-buffering.

__global__ void __launch_bounds__(256, 2) down_kernel(
        const __nv_bfloat16* __restrict__ Aq, const __nv_bfloat16* __restrict__ B,
        float* __restrict__ C, int N,
        const float* __restrict__ adq, const float* __restrict__ wdq) {
    extern __shared__ __align__(128) char smem[];
    const uint32_t sbase = smem_u32(smem);
    const int tid = threadIdx.x;
    const int lane = tid & 31;
    const int g = lane >> 2, tig = lane & 3;
    const int w = tid >> 5;
    const int wmb = (w >> 2) * 64;
    const int wnb = (w & 3) * 32;
    const int bm = blockIdx.y * 128, bn = blockIdx.x * 128;
    const size_t Kb = (size_t)Ff * 2;

    float acc[4][4][4];
#pragma unroll
    for (int mt = 0; mt < 4; mt++)
#pragma unroll
        for (int nt = 0; nt < 4; nt++)
#pragma unroll
            for (int k = 0; k < 4; k++) acc[mt][nt][k] = 0.0f;

    auto LOAD = [&](int kc, int s) {
        uint32_t sa = sbase + s * STG;
        const size_t kof = (size_t)kc * 128;
        const char* Ag = (const char*)Aq + (size_t)bm * Kb + kof;
        const char* Bg2 = (const char*)B + (size_t)bn * Kb + kof;
#pragma unroll
        for (int i = 0; i < 4; i++) {
            int idx = i * 256 + tid;
            int row = idx >> 3, ch = (idx & 7) * 16;
            cp16(sa + row * ROWB + ch, Ag + (size_t)row * Kb + ch);
        }
#pragma unroll
        for (int i = 0; i < 4; i++) {
            int idx = i * 256 + tid;
            int row = idx >> 3, ch = (idx & 7) * 16;
            cp16(sa + 18432 + row * ROWB + ch, Bg2 + (size_t)row * Kb + ch);
        }
        cp_commit();
    };

    const int NK = Ff / 64;   // 128
    LOAD(0, 0); LOAD(1, 1);

    const uint32_t a_row = (uint32_t)(lane & 15);
    const uint32_t a_k   = (uint32_t)((lane >> 4) * 16);
    const uint32_t b_row = (uint32_t)(((lane >> 4) << 3) + (lane & 7));
    const uint32_t b_k   = (uint32_t)(((lane >> 3) & 1) * 16);

    uint32_t af[2][4][4], bf[2][4][2];

    int cs = 0;
    for (int kc = 0; kc < NK; kc++) {
        cp_wait1();
        __syncthreads();
        int ls = cs + 2; if (ls >= 3) ls -= 3;
        if (kc + 2 < NK) LOAD(kc + 2, ls); else cp_commit();

        const uint32_t sa = sbase + cs * STG;
        const uint32_t sb = sa + 18432;

#pragma unroll
        for (int mt = 0; mt < 4; mt++)
            ldsm4(af[0][mt], sa + (uint32_t)(wmb + mt * 16 + a_row) * ROWB + a_k);
#pragma unroll
        for (int p = 0; p < 2; p++) {
            uint32_t t[4];
            ldsm4(t, sb + (uint32_t)(wnb + p * 16 + b_row) * ROWB + b_k);
            bf[0][2 * p][0] = t[0]; bf[0][2 * p][1] = t[1];
            bf[0][2 * p + 1][0] = t[2]; bf[0][2 * p + 1][1] = t[3];
        }

#pragma unroll
        for (int ks = 0; ks < 4; ks++) {
            const int cur = ks & 1, nxt = cur ^ 1;
            if (ks < 3) {
#pragma unroll
                for (int mt = 0; mt < 4; mt++)
                    ldsm4(af[nxt][mt], sa + (uint32_t)(wmb + mt * 16 + a_row) * ROWB
                                       + (uint32_t)((ks + 1) * 32) + a_k);
#pragma unroll
                for (int p = 0; p < 2; p++) {
                    uint32_t t[4];
                    ldsm4(t, sb + (uint32_t)(wnb + p * 16 + b_row) * ROWB
                             + (uint32_t)((ks + 1) * 32) + b_k);
                    bf[nxt][2 * p][0] = t[0]; bf[nxt][2 * p][1] = t[1];
                    bf[nxt][2 * p + 1][0] = t[2]; bf[nxt][2 * p + 1][1] = t[3];
                }
            }
#pragma unroll
            for (int mt = 0; mt < 4; mt++)
#pragma unroll
                for (int nt = 0; nt < 4; nt++)
                    mma_bf16(acc[mt][nt], af[cur][mt], bf[cur][nt]);
        }
        cs++; if (cs == 3) cs = 0;
    }

    const float wsc = *wdq;
#pragma unroll
    for (int mt = 0; mt < 4; mt++) {
        const int r0 = bm + wmb + mt * 16 + g;
        const int r1 = r0 + 8;
        const float s0 = adq[r0] * wsc;
        const float s1 = adq[r1] * wsc;
#pragma unroll
        for (int nt = 0; nt < 4; nt++) {
            const int c = bn + wnb + nt * 8 + tig * 2;
            *(float2*)&C[(size_t)r0 * N + c] =
                make_float2(acc[mt][nt][0] * s0, acc[mt][nt][1] * s0);
            *(float2*)&C[(size_t)r1 * N + c] =
                make_float2(acc[mt][nt][2] * s1, acc[mt][nt][3] * s1);
        }
    }
}

// ------------------------------- launch ------------------------------------

extern "C" void kernel_launch(void* const* d_in, const int* in_sizes, int n_in,
                              void* d_out, int out_size) {
    const float* x  = (const float*)d_in[0];
    const float* wg = (const float*)d_in[1];
    const float* wu = (const float*)d_in[2];
    const float* wd = (const float*)d_in[3];
    float* out = (float*)d_out;

    __nv_bfloat16 *p_wgb, *p_wub, *p_wdb, *p_xb, *p_hb;
    float *p_H, *p_xdq, *p_hdq, *p_wdq;
    cudaGetSymbolAddress((void**)&p_wgb, g_wgb);
    cudaGetSymbolAddress((void**)&p_wub, g_wub);
    cudaGetSymbolAddress((void**)&p_wdb, g_wdb);
    cudaGetSymbolAddress((void**)&p_xb,  g_xb);
    cudaGetSymbolAddress((void**)&p_hb,  g_hb);
    cudaGetSymbolAddress((void**)&p_H,   g_H);
    cudaGetSymbolAddress((void**)&p_xdq, g_xdq);
    cudaGetSymbolAddress((void**)&p_hdq, g_hdq);
    cudaGetSymbolAddress((void**)&p_wdq, g_wdq);

    cudaFuncSetAttribute(gateup_kernel,
                         cudaFuncAttributeMaxDynamicSharedMemorySize, GEMM_SMEM);
    cudaFuncSetAttribute(down_kernel,
                         cudaFuncAttributeMaxDynamicSharedMemorySize, GEMM_SMEM);

    const int nW = Ff * Dd;
    const int nW4 = nW / 4;

    zero_scalars_kernel<<<1, 32>>>();
    absum3_kernel<<<dim3(4096, 3), 256>>>(wg, wu, wd, nW4);
    wquant3_kernel<<<dim3(nW4 / 256, 3), 256>>>(wg, wu, wd, p_wgb, p_wub, p_wdb,
                                                nW4, 1.0 / (double)nW);

    actquant_x_kernel<<<Mm / 8, 256>>>(x, p_xb, p_xdq);

    // fused gate+up: H = silu(gate)*up   [4096, 8192]
    gateup_kernel<<<dim3(Ff / 64, Mm / 128), 256, GEMM_SMEM>>>(
        p_xb, p_wgb, p_wub, p_H, p_xdq);

    actquant_h_kernel<<<Mm, 256>>>(p_H, p_hb, p_hdq);

    // down -> d_out  [4096, 2048]
    down_kernel<<<dim3(Dd / 128, Mm / 128), 256, GEMM_SMEM>>>(
        p_hb, p_wdb, out, Dd, p_hdq, p_wdq + 2);
}

// round 13
// speedup vs baseline: 1.5654x; 1.5654x over previous
#include <cuda_runtime.h>
#include <cuda_bf16.h>
#include <math.h>
#include <stdint.h>

// ---------------------------------------------------------------------------
// BitNet b1.58 MLP, exact-integer formulation on legacy bf16 HMMA.
// R12 -> R13: GEMM mainloops reverted to R10 verbatim (fragment double-
// buffering caused register spills at launch_bounds(256,2) -> +755us).
// Preprocessing rebuilt for memory-level parallelism: grid-stride absum /
// wquant with ~16 float4 per thread, launched as per-tensor pairs so wquant
// re-reads the tensor from L2. actquant_h at 512 threads.
// Arithmetic unchanged: rel_err 5.449e-4 (integer-exact bf16 HMMA).
// ---------------------------------------------------------------------------

#define Dd 2048
#define Ff 8192
#define Mm 4096

#define ROWB 144                 // 64 bf16 = 128B data + 16B pad
#define STG  36864               // 256 rows * 144B per pipeline stage
#define GEMM_SMEM (3 * STG)      // 110592 -> 2 CTAs/SM

__device__ __align__(128) __nv_bfloat16 g_wgb[Ff * Dd];
__device__ __align__(128) __nv_bfloat16 g_wub[Ff * Dd];
__device__ __align__(128) __nv_bfloat16 g_wdb[Dd * Ff];
__device__ __align__(128) __nv_bfloat16 g_xb[Mm * Dd];
__device__ __align__(128) __nv_bfloat16 g_hb[(size_t)Mm * Ff];
__device__ __align__(128) float g_H[(size_t)Mm * Ff];
__device__ float  g_xdq[Mm];
__device__ float  g_hdq[Mm];
__device__ double g_wsum[3];
__device__ float  g_wdq[3];

// ------------------------------ utilities ----------------------------------

__device__ __forceinline__ uint32_t smem_u32(const void* p) {
    uint32_t a;
    asm("{ .reg .u64 t; cvta.to.shared.u64 t, %1; cvt.u32.u64 %0, t; }"
        : "=r"(a) : "l"(p));
    return a;
}
__device__ __forceinline__ void cp16(uint32_t dst, const void* src) {
    asm volatile("cp.async.cg.shared.global [%0], [%1], 16;"
                 :: "r"(dst), "l"(src) : "memory");
}
__device__ __forceinline__ void cp_commit() {
    asm volatile("cp.async.commit_group;" ::: "memory");
}
__device__ __forceinline__ void cp_wait1() {
    asm volatile("cp.async.wait_group 1;" ::: "memory");
}
__device__ __forceinline__ void ldsm4(uint32_t* r, uint32_t addr) {
    asm volatile("ldmatrix.sync.aligned.m8n8.x4.shared.b16 {%0,%1,%2,%3}, [%4];"
                 : "=r"(r[0]), "=r"(r[1]), "=r"(r[2]), "=r"(r[3]) : "r"(addr));
}
__device__ __forceinline__ void mma_bf16(float* c, const uint32_t* a, const uint32_t* b) {
    asm volatile(
        "mma.sync.aligned.m16n8k16.row.col.f32.bf16.bf16.f32 "
        "{%0,%1,%2,%3}, {%4,%5,%6,%7}, {%8,%9}, {%0,%1,%2,%3};"
        : "+f"(c[0]), "+f"(c[1]), "+f"(c[2]), "+f"(c[3])
        : "r"(a[0]), "r"(a[1]), "r"(a[2]), "r"(a[3]), "r"(b[0]), "r"(b[1]));
}

__device__ __forceinline__ double warpReduceSumD(double v) {
#pragma unroll
    for (int o = 16; o > 0; o >>= 1) v += __shfl_xor_sync(0xffffffffu, v, o);
    return v;
}
__device__ __forceinline__ float warpReduceMax(float v) {
#pragma unroll
    for (int o = 16; o > 0; o >>= 1) v = fmaxf(v, __shfl_xor_sync(0xffffffffu, v, o));
    return v;
}
__device__ __forceinline__ float silu_f(float g) {
    float sig;
    if (g >= 0.0f) {
        sig = 1.0f / (1.0f + expf(-g));
    } else {
        float e = expf(g);
        sig = e / (1.0f + e);
    }
    return g * sig;
}

// ---------------------------- small kernels --------------------------------

__global__ void zero_scalars_kernel() {
    if (threadIdx.x < 3) g_wsum[threadIdx.x] = 0.0;
}

// sum |W| (one tensor): grid-stride, unroll-4 for MLP, fp32 partials -> double
__global__ void __launch_bounds__(256) absum_kernel(
        const float* __restrict__ W, int n4, int slot) {
    float s = 0.0f;
    const float4* W4 = (const float4*)W;
    const int stride = gridDim.x * blockDim.x;
#pragma unroll 4
    for (int i = blockIdx.x * blockDim.x + threadIdx.x; i < n4; i += stride) {
        float4 w = W4[i];
        s += (fabsf(w.x) + fabsf(w.y)) + (fabsf(w.z) + fabsf(w.w));
    }
    double d = warpReduceSumD((double)s);
    __shared__ double rs[8];
    int warp = threadIdx.x >> 5, lane = threadIdx.x & 31;
    if (lane == 0) rs[warp] = d;
    __syncthreads();
    if (threadIdx.x == 0) {
        double t = 0.0;
#pragma unroll
        for (int i = 0; i < 8; i++) t += rs[i];
        atomicAdd(&g_wsum[slot], t);
    }
}

// ternary weight quant (one tensor) -> bf16 {-1,0,1}; grid-stride, unroll-4
__global__ void __launch_bounds__(256) wquant_kernel(
        const float* __restrict__ W, __nv_bfloat16* __restrict__ Q,
        int n4, int slot, double inv_n) {
    float mean = fmaxf((float)(g_wsum[slot] * inv_n), 1e-5f);
    float ws = 1.0f / mean;
    const int stride = gridDim.x * blockDim.x;
#pragma unroll 4
    for (int i = blockIdx.x * blockDim.x + threadIdx.x; i < n4; i += stride) {
        float4 w = ((const float4*)W)[i];
        float qx = rintf(fminf(fmaxf(w.x * ws, -1.0f), 1.0f));
        float qy = rintf(fminf(fmaxf(w.y * ws, -1.0f), 1.0f));
        float qz = rintf(fminf(fmaxf(w.z * ws, -1.0f), 1.0f));
        float qw = rintf(fminf(fmaxf(w.w * ws, -1.0f), 1.0f));
        __nv_bfloat162 lo = __nv_bfloat162(__float2bfloat16(qx), __float2bfloat16(qy));
        __nv_bfloat162 hi = __nv_bfloat162(__float2bfloat16(qz), __float2bfloat16(qw));
        uint2 pk;
        pk.x = *(uint32_t*)&lo;
        pk.y = *(uint32_t*)&hi;
        ((uint2*)Q)[i] = pk;
    }
    if (blockIdx.x == 0 && threadIdx.x == 0) g_wdq[slot] = 1.0f / ws;
}

// warp-per-row rmsnorm+quant for D=2048 (row held in registers, no smem)
__global__ void __launch_bounds__(256) actquant_x_kernel(
        const float* __restrict__ A, __nv_bfloat16* __restrict__ Q,
        float* __restrict__ DQ) {
    const int lane = threadIdx.x & 31;
    const int row = blockIdx.x * 8 + (threadIdx.x >> 5);
    const float4* a4 = (const float4*)(A + (size_t)row * Dd);
    uint2* q2 = (uint2*)(Q + (size_t)row * Dd);

    float4 v[16];
    double ss = 0.0;
    float mx = 0.0f;
#pragma unroll
    for (int p = 0; p < 16; p++) {
        v[p] = a4[p * 32 + lane];
        float q = (v[p].x * v[p].x + v[p].y * v[p].y)
                + (v[p].z * v[p].z + v[p].w * v[p].w);
        ss += (double)q;
        mx = fmaxf(mx, fmaxf(fmaxf(fabsf(v[p].x), fabsf(v[p].y)),
                             fmaxf(fabsf(v[p].z), fabsf(v[p].w))));
    }
    ss = warpReduceSumD(ss);
    mx = warpReduceMax(mx);
    float mean = (float)(ss / (double)Dd);
    float c = rsqrtf(mean + 1e-6f);
    float m = fmaxf(c * mx, 1e-5f);
    float scale = 127.0f / m;
    if (lane == 0) DQ[row] = 1.0f / scale;
#pragma unroll
    for (int p = 0; p < 16; p++) {
        float c0 = rintf(fminf(fmaxf((c * v[p].x) * scale, -128.0f), 127.0f));
        float c1 = rintf(fminf(fmaxf((c * v[p].y) * scale, -128.0f), 127.0f));
        float c2 = rintf(fminf(fmaxf((c * v[p].z) * scale, -128.0f), 127.0f));
        float c3 = rintf(fminf(fmaxf((c * v[p].w) * scale, -128.0f), 127.0f));
        __nv_bfloat162 lo = __nv_bfloat162(__float2bfloat16(c0), __float2bfloat16(c1));
        __nv_bfloat162 hi = __nv_bfloat162(__float2bfloat16(c2), __float2bfloat16(c3));
        uint2 pk;
        pk.x = *(uint32_t*)&lo;
        pk.y = *(uint32_t*)&hi;
        q2[p * 32 + lane] = pk;
    }
}

// block-per-row rmsnorm+quant for F=8192 (512 threads, 16 floats/thread)
__global__ void __launch_bounds__(512) actquant_h_kernel(
        const float* __restrict__ A, __nv_bfloat16* __restrict__ Q,
        float* __restrict__ DQ) {
    __shared__ double rs[16];
    __shared__ float rm[16];
    __shared__ float s_c, s_scale;
    const int tid = threadIdx.x;
    const int row = blockIdx.x;
    const float4* a4 = (const float4*)(A + (size_t)row * Ff);
    uint2* q2 = (uint2*)(Q + (size_t)row * Ff);

    float4 v[4];
    double ss = 0.0;
    float mx = 0.0f;
#pragma unroll
    for (int p = 0; p < 4; p++) {
        v[p] = a4[p * 512 + tid];
        float q = (v[p].x * v[p].x + v[p].y * v[p].y)
                + (v[p].z * v[p].z + v[p].w * v[p].w);
        ss += (double)q;
        mx = fmaxf(mx, fmaxf(fmaxf(fabsf(v[p].x), fabsf(v[p].y)),
                             fmaxf(fabsf(v[p].z), fabsf(v[p].w))));
    }
    ss = warpReduceSumD(ss);
    mx = warpReduceMax(mx);
    int warp = tid >> 5, lane = tid & 31;
    if (lane == 0) { rs[warp] = ss; rm[warp] = mx; }
    __syncthreads();
    if (tid == 0) {
        double S = 0.0;
        float Mx = 0.0f;
#pragma unroll
        for (int i = 0; i < 16; i++) { S += rs[i]; Mx = fmaxf(Mx, rm[i]); }
        float mean = (float)(S / (double)Ff);
        float c = rsqrtf(mean + 1e-6f);
        float m = fmaxf(c * Mx, 1e-5f);
        float scale = 127.0f / m;
        s_c = c; s_scale = scale;
        DQ[row] = 1.0f / scale;
    }
    __syncthreads();
    const float c = s_c, scale = s_scale;
#pragma unroll
    for (int p = 0; p < 4; p++) {
        float c0 = rintf(fminf(fmaxf((c * v[p].x) * scale, -128.0f), 127.0f));
        float c1 = rintf(fminf(fmaxf((c * v[p].y) * scale, -128.0f), 127.0f));
        float c2 = rintf(fminf(fmaxf((c * v[p].z) * scale, -128.0f), 127.0f));
        float c3 = rintf(fminf(fmaxf((c * v[p].w) * scale, -128.0f), 127.0f));
        __nv_bfloat162 lo = __nv_bfloat162(__float2bfloat16(c0), __float2bfloat16(c1));
        __nv_bfloat162 hi = __nv_bfloat162(__float2bfloat16(c2), __float2bfloat16(c3));
        uint2 pk;
        pk.x = *(uint32_t*)&lo;
        pk.y = *(uint32_t*)&hi;
        q2[p * 512 + tid] = pk;
    }
}

// --------------------- fused gate+up bf16 HMMA GEMM ------------------------
// R10 mainloop verbatim: single-buffered fragments, 64x32 warp tiles,
// 2 CTAs/SM. Epilogue: gate warps stage silu(g) in smem; up warps write H.

__global__ void __launch_bounds__(256, 2) gateup_kernel(
        const __nv_bfloat16* __restrict__ Aq,
        const __nv_bfloat16* __restrict__ Bg,
        const __nv_bfloat16* __restrict__ Bu,
        float* __restrict__ H,
        const float* __restrict__ adq) {
    extern __shared__ __align__(128) char smem[];
    const uint32_t sbase = smem_u32(smem);
    const int tid = threadIdx.x;
    const int lane = tid & 31;
    const int g = lane >> 2, tig = lane & 3;
    const int w = tid >> 5;
    const int uw = w & 3;
    const int isUp = w >> 2;
    const int wmb = (uw >> 1) * 64;
    const int wnb = (uw & 1) * 32;
    const int bm = blockIdx.y * 128, bn = blockIdx.x * 64;
    const size_t Kb = (size_t)Dd * 2;

    float acc[4][4][4];
#pragma unroll
    for (int mt = 0; mt < 4; mt++)
#pragma unroll
        for (int nt = 0; nt < 4; nt++)
#pragma unroll
            for (int k = 0; k < 4; k++) acc[mt][nt][k] = 0.0f;

    auto LOAD = [&](int kc, int s) {
        uint32_t sa = sbase + s * STG;
        const size_t kof = (size_t)kc * 128;
        const char* Ag = (const char*)Aq + (size_t)bm * Kb + kof;
        const char* Gg = (const char*)Bg + (size_t)bn * Kb + kof;
        const char* Ug = (const char*)Bu + (size_t)bn * Kb + kof;
#pragma unroll
        for (int i = 0; i < 4; i++) {
            int idx = i * 256 + tid;
            int row = idx >> 3, ch = (idx & 7) * 16;
            cp16(sa + row * ROWB + ch, Ag + (size_t)row * Kb + ch);
        }
#pragma unroll
        for (int i = 0; i < 2; i++) {
            int idx = i * 256 + tid;
            int row = idx >> 3, ch = (idx & 7) * 16;
            cp16(sa + 18432 + row * ROWB + ch, Gg + (size_t)row * Kb + ch);
        }
#pragma unroll
        for (int i = 0; i < 2; i++) {
            int idx = i * 256 + tid;
            int row = idx >> 3, ch = (idx & 7) * 16;
            cp16(sa + 27648 + row * ROWB + ch, Ug + (size_t)row * Kb + ch);
        }
        cp_commit();
    };

    const int NK = Dd / 64;   // 32
    LOAD(0, 0); LOAD(1, 1);

    const uint32_t a_row = (uint32_t)(lane & 15);
    const uint32_t a_k   = (uint32_t)((lane >> 4) * 16);
    const uint32_t b_row = (uint32_t)(((lane >> 4) << 3) + (lane & 7));
    const uint32_t b_k   = (uint32_t)(((lane >> 3) & 1) * 16);

    int cs = 0;
    for (int kc = 0; kc < NK; kc++) {
        cp_wait1();
        __syncthreads();
        int ls = cs + 2; if (ls >= 3) ls -= 3;
        if (kc + 2 < NK) LOAD(kc + 2, ls); else cp_commit();

        const uint32_t sa = sbase + cs * STG;
        const uint32_t sbW = sa + 18432 + (uint32_t)isUp * 9216;
#pragma unroll
        for (int ks = 0; ks < 4; ks++) {
            uint32_t af[4][4], bf[4][2];
#pragma unroll
            for (int mt = 0; mt < 4; mt++)
                ldsm4(af[mt], sa + (uint32_t)(wmb + mt * 16 + a_row) * ROWB
                              + (uint32_t)(ks * 32) + a_k);
#pragma unroll
            for (int p = 0; p < 2; p++) {
                uint32_t t[4];
                ldsm4(t, sbW + (uint32_t)(wnb + p * 16 + b_row) * ROWB
                         + (uint32_t)(ks * 32) + b_k);
                bf[2 * p][0] = t[0]; bf[2 * p][1] = t[1];
                bf[2 * p + 1][0] = t[2]; bf[2 * p + 1][1] = t[3];
            }
#pragma unroll
            for (int mt = 0; mt < 4; mt++)
#pragma unroll
                for (int nt = 0; nt < 4; nt++)
                    mma_bf16(acc[mt][nt], af[mt], bf[nt]);
        }
        cs++; if (cs == 3) cs = 0;
    }

    // ---- epilogue: exchange silu(g) via smem, write H = silu(g)*u ----
    __syncthreads();
    float* hstage = (float*)smem;    // [128][68]
    if (!isUp) {
        const float wgs = g_wdq[0];
#pragma unroll
        for (int mt = 0; mt < 4; mt++) {
            int r0 = wmb + mt * 16 + g;
            float s0 = adq[bm + r0] * wgs;
            float s1 = adq[bm + r0 + 8] * wgs;
#pragma unroll
            for (int nt = 0; nt < 4; nt++) {
                int c = wnb + nt * 8 + tig * 2;
                hstage[r0 * 68 + c]           = silu_f(acc[mt][nt][0] * s0);
                hstage[r0 * 68 + c + 1]       = silu_f(acc[mt][nt][1] * s0);
                hstage[(r0 + 8) * 68 + c]     = silu_f(acc[mt][nt][2] * s1);
                hstage[(r0 + 8) * 68 + c + 1] = silu_f(acc[mt][nt][3] * s1);
            }
        }
    }
    __syncthreads();
    if (isUp) {
        const float wus = g_wdq[1];
#pragma unroll
        for (int mt = 0; mt < 4; mt++) {
            int r0 = wmb + mt * 16 + g;
            float s0 = adq[bm + r0] * wus;
            float s1 = adq[bm + r0 + 8] * wus;
#pragma unroll
            for (int nt = 0; nt < 4; nt++) {
                int c = wnb + nt * 8 + tig * 2;
                float v00 = acc[mt][nt][0] * s0 * hstage[r0 * 68 + c];
                float v01 = acc[mt][nt][1] * s0 * hstage[r0 * 68 + c + 1];
                float v10 = acc[mt][nt][2] * s1 * hstage[(r0 + 8) * 68 + c];
                float v11 = acc[mt][nt][3] * s1 * hstage[(r0 + 8) * 68 + c + 1];
                *(float2*)&H[(size_t)(bm + r0) * Ff + bn + c] = make_float2(v00, v01);
                *(float2*)&H[(size_t)(bm + r0 + 8) * Ff + bn + c] = make_float2(v10, v11);
            }
        }
    }
}

// --------------------------- down bf16 HMMA GEMM ---------------------------
// R10 mainloop verbatim: block 128x128, 8 warps (2x4), warp tile 64x32.

__global__ void __launch_bounds__(256, 2) down_kernel(
        const __nv_bfloat16* __restrict__ Aq, const __nv_bfloat16* __restrict__ B,
        float* __restrict__ C, int N,
        const float* __restrict__ adq, const float* __restrict__ wdq) {
    extern __shared__ __align__(128) char smem[];
    const uint32_t sbase = smem_u32(smem);
    const int tid = threadIdx.x;
    const int lane = tid & 31;
    const int g = lane >> 2, tig = lane & 3;
    const int w = tid >> 5;
    const int wmb = (w >> 2) * 64;
    const int wnb = (w & 3) * 32;
    const int bm = blockIdx.y * 128, bn = blockIdx.x * 128;
    const size_t Kb = (size_t)Ff * 2;

    float acc[4][4][4];
#pragma unroll
    for (int mt = 0; mt < 4; mt++)
#pragma unroll
        for (int nt = 0; nt < 4; nt++)
#pragma unroll
            for (int k = 0; k < 4; k++) acc[mt][nt][k] = 0.0f;

    auto LOAD = [&](int kc, int s) {
        uint32_t sa = sbase + s * STG;
        const size_t kof = (size_t)kc * 128;
        const char* Ag = (const char*)Aq + (size_t)bm * Kb + kof;
        const char* Bg2 = (const char*)B + (size_t)bn * Kb + kof;
#pragma unroll
        for (int i = 0; i < 4; i++) {
            int idx = i * 256 + tid;
            int row = idx >> 3, ch = (idx & 7) * 16;
            cp16(sa + row * ROWB + ch, Ag + (size_t)row * Kb + ch);
        }
#pragma unroll
        for (int i = 0; i < 4; i++) {
            int idx = i * 256 + tid;
            int row = idx >> 3, ch = (idx & 7) * 16;
            cp16(sa + 18432 + row * ROWB + ch, Bg2 + (size_t)row * Kb + ch);
        }
        cp_commit();
    };

    const int NK = Ff / 64;   // 128
    LOAD(0, 0); LOAD(1, 1);

    const uint32_t a_row = (uint32_t)(lane & 15);
    const uint32_t a_k   = (uint32_t)((lane >> 4) * 16);
    const uint32_t b_row = (uint32_t)(((lane >> 4) << 3) + (lane & 7));
    const uint32_t b_k   = (uint32_t)(((lane >> 3) & 1) * 16);

    int cs = 0;
    for (int kc = 0; kc < NK; kc++) {
        cp_wait1();
        __syncthreads();
        int ls = cs + 2; if (ls >= 3) ls -= 3;
        if (kc + 2 < NK) LOAD(kc + 2, ls); else cp_commit();

        const uint32_t sa = sbase + cs * STG;
        const uint32_t sb = sa + 18432;
#pragma unroll
        for (int ks = 0; ks < 4; ks++) {
            uint32_t af[4][4], bf[4][2];
#pragma unroll
            for (int mt = 0; mt < 4; mt++)
                ldsm4(af[mt], sa + (uint32_t)(wmb + mt * 16 + a_row) * ROWB
                              + (uint32_t)(ks * 32) + a_k);
#pragma unroll
            for (int p = 0; p < 2; p++) {
                uint32_t t[4];
                ldsm4(t, sb + (uint32_t)(wnb + p * 16 + b_row) * ROWB
                         + (uint32_t)(ks * 32) + b_k);
                bf[2 * p][0] = t[0]; bf[2 * p][1] = t[1];
                bf[2 * p + 1][0] = t[2]; bf[2 * p + 1][1] = t[3];
            }
#pragma unroll
            for (int mt = 0; mt < 4; mt++)
#pragma unroll
                for (int nt = 0; nt < 4; nt++)
                    mma_bf16(acc[mt][nt], af[mt], bf[nt]);
        }
        cs++; if (cs == 3) cs = 0;
    }

    const float wsc = *wdq;
#pragma unroll
    for (int mt = 0; mt < 4; mt++) {
        const int r0 = bm + wmb + mt * 16 + g;
        const int r1 = r0 + 8;
        const float s0 = adq[r0] * wsc;
        const float s1 = adq[r1] * wsc;
#pragma unroll
        for (int nt = 0; nt < 4; nt++) {
            const int c = bn + wnb + nt * 8 + tig * 2;
            *(float2*)&C[(size_t)r0 * N + c] =
                make_float2(acc[mt][nt][0] * s0, acc[mt][nt][1] * s0);
            *(float2*)&C[(size_t)r1 * N + c] =
                make_float2(acc[mt][nt][2] * s1, acc[mt][nt][3] * s1);
        }
    }
}

// ------------------------------- launch ------------------------------------

extern "C" void kernel_launch(void* const* d_in, const int* in_sizes, int n_in,
                              void* d_out, int out_size) {
    const float* x  = (const float*)d_in[0];
    const float* wg = (const float*)d_in[1];
    const float* wu = (const float*)d_in[2];
    const float* wd = (const float*)d_in[3];
    float* out = (float*)d_out;

    __nv_bfloat16 *p_wgb, *p_wub, *p_wdb, *p_xb, *p_hb;
    float *p_H, *p_xdq, *p_hdq, *p_wdq;
    cudaGetSymbolAddress((void**)&p_wgb, g_wgb);
    cudaGetSymbolAddress((void**)&p_wub, g_wub);
    cudaGetSymbolAddress((void**)&p_wdb, g_wdb);
    cudaGetSymbolAddress((void**)&p_xb,  g_xb);
    cudaGetSymbolAddress((void**)&p_hb,  g_hb);
    cudaGetSymbolAddress((void**)&p_H,   g_H);
    cudaGetSymbolAddress((void**)&p_xdq, g_xdq);
    cudaGetSymbolAddress((void**)&p_hdq, g_hdq);
    cudaGetSymbolAddress((void**)&p_wdq, g_wdq);

    cudaFuncSetAttribute(gateup_kernel,
                         cudaFuncAttributeMaxDynamicSharedMemorySize, GEMM_SMEM);
    cudaFuncSetAttribute(down_kernel,
                         cudaFuncAttributeMaxDynamicSharedMemorySize, GEMM_SMEM);

    const int nW = Ff * Dd;
    const int nW4 = nW / 4;
    const double inv_n = 1.0 / (double)nW;

    zero_scalars_kernel<<<1, 32>>>();

    // per-tensor absum -> wquant pairs (wquant re-reads the tensor from L2)
    absum_kernel<<<2048, 256>>>(wg, nW4, 0);
    wquant_kernel<<<2048, 256>>>(wg, p_wgb, nW4, 0, inv_n);
    absum_kernel<<<2048, 256>>>(wu, nW4, 1);
    wquant_kernel<<<2048, 256>>>(wu, p_wub, nW4, 1, inv_n);
    absum_kernel<<<2048, 256>>>(wd, nW4, 2);
    wquant_kernel<<<2048, 256>>>(wd, p_wdb, nW4, 2, inv_n);

    actquant_x_kernel<<<Mm / 8, 256>>>(x, p_xb, p_xdq);

    // fused gate+up: H = silu(gate)*up   [4096, 8192]
    gateup_kernel<<<dim3(Ff / 64, Mm / 128), 256, GEMM_SMEM>>>(
        p_xb, p_wgb, p_wub, p_H, p_xdq);

    actquant_h_kernel<<<Mm, 512>>>(p_H, p_hb, p_hdq);

    // down -> d_out  [4096, 2048]
    down_kernel<<<dim3(Dd / 128, Mm / 128), 256, GEMM_SMEM>>>(
        p_hb, p_wdb, out, Dd, p_hdq, p_wdq + 2);
}

// round 14
// speedup vs baseline: 1.5674x; 1.0013x over previous
#include <cuda_runtime.h>
#include <cuda_bf16.h>
#include <math.h>
#include <stdint.h>

// ---------------------------------------------------------------------------
// BitNet b1.58 MLP, exact-integer formulation on legacy bf16 HMMA.
// R13 -> R14: pure launch reordering so gateup_kernel is the 6th launch
// (ncu -s 5 -c 1 captures it): actquant_x (now also zeroes g_wsum) first,
// gate/up absum+wquant pairs next, gateup 6th, down-weight quant deferred
// to after gateup (still before down_kernel). Kernels themselves unchanged
// from R13. rel_err 5.449e-4 bit-identical.
// ---------------------------------------------------------------------------

#define Dd 2048
#define Ff 8192
#define Mm 4096

#define ROWB 144                 // 64 bf16 = 128B data + 16B pad
#define STG  36864               // 256 rows * 144B per pipeline stage
#define GEMM_SMEM (3 * STG)      // 110592 -> 2 CTAs/SM

__device__ __align__(128) __nv_bfloat16 g_wgb[Ff * Dd];
__device__ __align__(128) __nv_bfloat16 g_wub[Ff * Dd];
__device__ __align__(128) __nv_bfloat16 g_wdb[Dd * Ff];
__device__ __align__(128) __nv_bfloat16 g_xb[Mm * Dd];
__device__ __align__(128) __nv_bfloat16 g_hb[(size_t)Mm * Ff];
__device__ __align__(128) float g_H[(size_t)Mm * Ff];
__device__ float  g_xdq[Mm];
__device__ float  g_hdq[Mm];
__device__ double g_wsum[3];
__device__ float  g_wdq[3];

// ------------------------------ utilities ----------------------------------

__device__ __forceinline__ uint32_t smem_u32(const void* p) {
    uint32_t a;
    asm("{ .reg .u64 t; cvta.to.shared.u64 t, %1; cvt.u32.u64 %0, t; }"
        : "=r"(a) : "l"(p));
    return a;
}
__device__ __forceinline__ void cp16(uint32_t dst, const void* src) {
    asm volatile("cp.async.cg.shared.global [%0], [%1], 16;"
                 :: "r"(dst), "l"(src) : "memory");
}
__device__ __forceinline__ void cp_commit() {
    asm volatile("cp.async.commit_group;" ::: "memory");
}
__device__ __forceinline__ void cp_wait1() {
    asm volatile("cp.async.wait_group 1;" ::: "memory");
}
__device__ __forceinline__ void ldsm4(uint32_t* r, uint32_t addr) {
    asm volatile("ldmatrix.sync.aligned.m8n8.x4.shared.b16 {%0,%1,%2,%3}, [%4];"
                 : "=r"(r[0]), "=r"(r[1]), "=r"(r[2]), "=r"(r[3]) : "r"(addr));
}
__device__ __forceinline__ void mma_bf16(float* c, const uint32_t* a, const uint32_t* b) {
    asm volatile(
        "mma.sync.aligned.m16n8k16.row.col.f32.bf16.bf16.f32 "
        "{%0,%1,%2,%3}, {%4,%5,%6,%7}, {%8,%9}, {%0,%1,%2,%3};"
        : "+f"(c[0]), "+f"(c[1]), "+f"(c[2]), "+f"(c[3])
        : "r"(a[0]), "r"(a[1]), "r"(a[2]), "r"(a[3]), "r"(b[0]), "r"(b[1]));
}

__device__ __forceinline__ double warpReduceSumD(double v) {
#pragma unroll
    for (int o = 16; o > 0; o >>= 1) v += __shfl_xor_sync(0xffffffffu, v, o);
    return v;
}
__device__ __forceinline__ float warpReduceMax(float v) {
#pragma unroll
    for (int o = 16; o > 0; o >>= 1) v = fmaxf(v, __shfl_xor_sync(0xffffffffu, v, o));
    return v;
}
__device__ __forceinline__ float silu_f(float g) {
    float sig;
    if (g >= 0.0f) {
        sig = 1.0f / (1.0f + expf(-g));
    } else {
        float e = expf(g);
        sig = e / (1.0f + e);
    }
    return g * sig;
}

// ---------------------------- small kernels --------------------------------

// sum |W| (one tensor): grid-stride, unroll-4 for MLP, fp32 partials -> double
__global__ void __launch_bounds__(256) absum_kernel(
        const float* __restrict__ W, int n4, int slot) {
    float s = 0.0f;
    const float4* W4 = (const float4*)W;
    const int stride = gridDim.x * blockDim.x;
#pragma unroll 4
    for (int i = blockIdx.x * blockDim.x + threadIdx.x; i < n4; i += stride) {
        float4 w = W4[i];
        s += (fabsf(w.x) + fabsf(w.y)) + (fabsf(w.z) + fabsf(w.w));
    }
    double d = warpReduceSumD((double)s);
    __shared__ double rs[8];
    int warp = threadIdx.x >> 5, lane = threadIdx.x & 31;
    if (lane == 0) rs[warp] = d;
    __syncthreads();
    if (threadIdx.x == 0) {
        double t = 0.0;
#pragma unroll
        for (int i = 0; i < 8; i++) t += rs[i];
        atomicAdd(&g_wsum[slot], t);
    }
}

// ternary weight quant (one tensor) -> bf16 {-1,0,1}; grid-stride, unroll-4
__global__ void __launch_bounds__(256) wquant_kernel(
        const float* __restrict__ W, __nv_bfloat16* __restrict__ Q,
        int n4, int slot, double inv_n) {
    float mean = fmaxf((float)(g_wsum[slot] * inv_n), 1e-5f);
    float ws = 1.0f / mean;
    const int stride = gridDim.x * blockDim.x;
#pragma unroll 4
    for (int i = blockIdx.x * blockDim.x + threadIdx.x; i < n4; i += stride) {
        float4 w = ((const float4*)W)[i];
        float qx = rintf(fminf(fmaxf(w.x * ws, -1.0f), 1.0f));
        float qy = rintf(fminf(fmaxf(w.y * ws, -1.0f), 1.0f));
        float qz = rintf(fminf(fmaxf(w.z * ws, -1.0f), 1.0f));
        float qw = rintf(fminf(fmaxf(w.w * ws, -1.0f), 1.0f));
        __nv_bfloat162 lo = __nv_bfloat162(__float2bfloat16(qx), __float2bfloat16(qy));
        __nv_bfloat162 hi = __nv_bfloat162(__float2bfloat16(qz), __float2bfloat16(qw));
        uint2 pk;
        pk.x = *(uint32_t*)&lo;
        pk.y = *(uint32_t*)&hi;
        ((uint2*)Q)[i] = pk;
    }
    if (blockIdx.x == 0 && threadIdx.x == 0) g_wdq[slot] = 1.0f / ws;
}

// warp-per-row rmsnorm+quant for D=2048 (row held in registers, no smem).
// Launch #1: also zeroes g_wsum (weights untouched by this kernel; the
// subsequent absum launches are stream-ordered after it).
__global__ void __launch_bounds__(256) actquant_x_kernel(
        const float* __restrict__ A, __nv_bfloat16* __restrict__ Q,
        float* __restrict__ DQ) {
    if (blockIdx.x == 0 && threadIdx.x == 0) {
        g_wsum[0] = 0.0; g_wsum[1] = 0.0; g_wsum[2] = 0.0;
    }
    const int lane = threadIdx.x & 31;
    const int row = blockIdx.x * 8 + (threadIdx.x >> 5);
    const float4* a4 = (const float4*)(A + (size_t)row * Dd);
    uint2* q2 = (uint2*)(Q + (size_t)row * Dd);

    float4 v[16];
    double ss = 0.0;
    float mx = 0.0f;
#pragma unroll
    for (int p = 0; p < 16; p++) {
        v[p] = a4[p * 32 + lane];
        float q = (v[p].x * v[p].x + v[p].y * v[p].y)
                + (v[p].z * v[p].z + v[p].w * v[p].w);
        ss += (double)q;
        mx = fmaxf(mx, fmaxf(fmaxf(fabsf(v[p].x), fabsf(v[p].y)),
                             fmaxf(fabsf(v[p].z), fabsf(v[p].w))));
    }
    ss = warpReduceSumD(ss);
    mx = warpReduceMax(mx);
    float mean = (float)(ss / (double)Dd);
    float c = rsqrtf(mean + 1e-6f);
    float m = fmaxf(c * mx, 1e-5f);
    float scale = 127.0f / m;
    if (lane == 0) DQ[row] = 1.0f / scale;
#pragma unroll
    for (int p = 0; p < 16; p++) {
        float c0 = rintf(fminf(fmaxf((c * v[p].x) * scale, -128.0f), 127.0f));
        float c1 = rintf(fminf(fmaxf((c * v[p].y) * scale, -128.0f), 127.0f));
        float c2 = rintf(fminf(fmaxf((c * v[p].z) * scale, -128.0f), 127.0f));
        float c3 = rintf(fminf(fmaxf((c * v[p].w) * scale, -128.0f), 127.0f));
        __nv_bfloat162 lo = __nv_bfloat162(__float2bfloat16(c0), __float2bfloat16(c1));
        __nv_bfloat162 hi = __nv_bfloat162(__float2bfloat16(c2), __float2bfloat16(c3));
        uint2 pk;
        pk.x = *(uint32_t*)&lo;
        pk.y = *(uint32_t*)&hi;
        q2[p * 32 + lane] = pk;
    }
}

// block-per-row rmsnorm+quant for F=8192 (512 threads, 16 floats/thread)
__global__ void __launch_bounds__(512) actquant_h_kernel(
        const float* __restrict__ A, __nv_bfloat16* __restrict__ Q,
        float* __restrict__ DQ) {
    __shared__ double rs[16];
    __shared__ float rm[16];
    __shared__ float s_c, s_scale;
    const int tid = threadIdx.x;
    const int row = blockIdx.x;
    const float4* a4 = (const float4*)(A + (size_t)row * Ff);
    uint2* q2 = (uint2*)(Q + (size_t)row * Ff);

    float4 v[4];
    double ss = 0.0;
    float mx = 0.0f;
#pragma unroll
    for (int p = 0; p < 4; p++) {
        v[p] = a4[p * 512 + tid];
        float q = (v[p].x * v[p].x + v[p].y * v[p].y)
                + (v[p].z * v[p].z + v[p].w * v[p].w);
        ss += (double)q;
        mx = fmaxf(mx, fmaxf(fmaxf(fabsf(v[p].x), fabsf(v[p].y)),
                             fmaxf(fabsf(v[p].z), fabsf(v[p].w))));
    }
    ss = warpReduceSumD(ss);
    mx = warpReduceMax(mx);
    int warp = tid >> 5, lane = tid & 31;
    if (lane == 0) { rs[warp] = ss; rm[warp] = mx; }
    __syncthreads();
    if (tid == 0) {
        double S = 0.0;
        float Mx = 0.0f;
#pragma unroll
        for (int i = 0; i < 16; i++) { S += rs[i]; Mx = fmaxf(Mx, rm[i]); }
        float mean = (float)(S / (double)Ff);
        float c = rsqrtf(mean + 1e-6f);
        float m = fmaxf(c * Mx, 1e-5f);
        float scale = 127.0f / m;
        s_c = c; s_scale = scale;
        DQ[row] = 1.0f / scale;
    }
    __syncthreads();
    const float c = s_c, scale = s_scale;
#pragma unroll
    for (int p = 0; p < 4; p++) {
        float c0 = rintf(fminf(fmaxf((c * v[p].x) * scale, -128.0f), 127.0f));
        float c1 = rintf(fminf(fmaxf((c * v[p].y) * scale, -128.0f), 127.0f));
        float c2 = rintf(fminf(fmaxf((c * v[p].z) * scale, -128.0f), 127.0f));
        float c3 = rintf(fminf(fmaxf((c * v[p].w) * scale, -128.0f), 127.0f));
        __nv_bfloat162 lo = __nv_bfloat162(__float2bfloat16(c0), __float2bfloat16(c1));
        __nv_bfloat162 hi = __nv_bfloat162(__float2bfloat16(c2), __float2bfloat16(c3));
        uint2 pk;
        pk.x = *(uint32_t*)&lo;
        pk.y = *(uint32_t*)&hi;
        q2[p * 512 + tid] = pk;
    }
}

// --------------------- fused gate+up bf16 HMMA GEMM ------------------------
// R10 mainloop: single-buffered fragments, 64x32 warp tiles, 2 CTAs/SM.
// Epilogue: gate warps stage silu(g) in smem; up warps multiply, write H.

__global__ void __launch_bounds__(256, 2) gateup_kernel(
        const __nv_bfloat16* __restrict__ Aq,
        const __nv_bfloat16* __restrict__ Bg,
        const __nv_bfloat16* __restrict__ Bu,
        float* __restrict__ H,
        const float* __restrict__ adq) {
    extern __shared__ __align__(128) char smem[];
    const uint32_t sbase = smem_u32(smem);
    const int tid = threadIdx.x;
    const int lane = tid & 31;
    const int g = lane >> 2, tig = lane & 3;
    const int w = tid >> 5;
    const int uw = w & 3;
    const int isUp = w >> 2;
    const int wmb = (uw >> 1) * 64;
    const int wnb = (uw & 1) * 32;
    const int bm = blockIdx.y * 128, bn = blockIdx.x * 64;
    const size_t Kb = (size_t)Dd * 2;

    float acc[4][4][4];
#pragma unroll
    for (int mt = 0; mt < 4; mt++)
#pragma unroll
        for (int nt = 0; nt < 4; nt++)
#pragma unroll
            for (int k = 0; k < 4; k++) acc[mt][nt][k] = 0.0f;

    auto LOAD = [&](int kc, int s) {
        uint32_t sa = sbase + s * STG;
        const size_t kof = (size_t)kc * 128;
        const char* Ag = (const char*)Aq + (size_t)bm * Kb + kof;
        const char* Gg = (const char*)Bg + (size_t)bn * Kb + kof;
        const char* Ug = (const char*)Bu + (size_t)bn * Kb + kof;
#pragma unroll
        for (int i = 0; i < 4; i++) {
            int idx = i * 256 + tid;
            int row = idx >> 3, ch = (idx & 7) * 16;
            cp16(sa + row * ROWB + ch, Ag + (size_t)row * Kb + ch);
        }
#pragma unroll
        for (int i = 0; i < 2; i++) {
            int idx = i * 256 + tid;
            int row = idx >> 3, ch = (idx & 7) * 16;
            cp16(sa + 18432 + row * ROWB + ch, Gg + (size_t)row * Kb + ch);
        }
#pragma unroll
        for (int i = 0; i < 2; i++) {
            int idx = i * 256 + tid;
            int row = idx >> 3, ch = (idx & 7) * 16;
            cp16(sa + 27648 + row * ROWB + ch, Ug + (size_t)row * Kb + ch);
        }
        cp_commit();
    };

    const int NK = Dd / 64;   // 32
    LOAD(0, 0); LOAD(1, 1);

    const uint32_t a_row = (uint32_t)(lane & 15);
    const uint32_t a_k   = (uint32_t)((lane >> 4) * 16);
    const uint32_t b_row = (uint32_t)(((lane >> 4) << 3) + (lane & 7));
    const uint32_t b_k   = (uint32_t)(((lane >> 3) & 1) * 16);

    int cs = 0;
    for (int kc = 0; kc < NK; kc++) {
        cp_wait1();
        __syncthreads();
        int ls = cs + 2; if (ls >= 3) ls -= 3;
        if (kc + 2 < NK) LOAD(kc + 2, ls); else cp_commit();

        const uint32_t sa = sbase + cs * STG;
        const uint32_t sbW = sa + 18432 + (uint32_t)isUp * 9216;
#pragma unroll
        for (int ks = 0; ks < 4; ks++) {
            uint32_t af[4][4], bf[4][2];
#pragma unroll
            for (int mt = 0; mt < 4; mt++)
                ldsm4(af[mt], sa + (uint32_t)(wmb + mt * 16 + a_row) * ROWB
                              + (uint32_t)(ks * 32) + a_k);
#pragma unroll
            for (int p = 0; p < 2; p++) {
                uint32_t t[4];
                ldsm4(t, sbW + (uint32_t)(wnb + p * 16 + b_row) * ROWB
                         + (uint32_t)(ks * 32) + b_k);
                bf[2 * p][0] = t[0]; bf[2 * p][1] = t[1];
                bf[2 * p + 1][0] = t[2]; bf[2 * p + 1][1] = t[3];
            }
#pragma unroll
            for (int mt = 0; mt < 4; mt++)
#pragma unroll
                for (int nt = 0; nt < 4; nt++)
                    mma_bf16(acc[mt][nt], af[mt], bf[nt]);
        }
        cs++; if (cs == 3) cs = 0;
    }

    // ---- epilogue: exchange silu(g) via smem, write H = silu(g)*u ----
    __syncthreads();
    float* hstage = (float*)smem;    // [128][68]
    if (!isUp) {
        const float wgs = g_wdq[0];
#pragma unroll
        for (int mt = 0; mt < 4; mt++) {
            int r0 = wmb + mt * 16 + g;
            float s0 = adq[bm + r0] * wgs;
            float s1 = adq[bm + r0 + 8] * wgs;
#pragma unroll
            for (int nt = 0; nt < 4; nt++) {
                int c = wnb + nt * 8 + tig * 2;
                hstage[r0 * 68 + c]           = silu_f(acc[mt][nt][0] * s0);
                hstage[r0 * 68 + c + 1]       = silu_f(acc[mt][nt][1] * s0);
                hstage[(r0 + 8) * 68 + c]     = silu_f(acc[mt][nt][2] * s1);
                hstage[(r0 + 8) * 68 + c + 1] = silu_f(acc[mt][nt][3] * s1);
            }
        }
    }
    __syncthreads();
    if (isUp) {
        const float wus = g_wdq[1];
#pragma unroll
        for (int mt = 0; mt < 4; mt++) {
            int r0 = wmb + mt * 16 + g;
            float s0 = adq[bm + r0] * wus;
            float s1 = adq[bm + r0 + 8] * wus;
#pragma unroll
            for (int nt = 0; nt < 4; nt++) {
                int c = wnb + nt * 8 + tig * 2;
                float v00 = acc[mt][nt][0] * s0 * hstage[r0 * 68 + c];
                float v01 = acc[mt][nt][1] * s0 * hstage[r0 * 68 + c + 1];
                float v10 = acc[mt][nt][2] * s1 * hstage[(r0 + 8) * 68 + c];
                float v11 = acc[mt][nt][3] * s1 * hstage[(r0 + 8) * 68 + c + 1];
                *(float2*)&H[(size_t)(bm + r0) * Ff + bn + c] = make_float2(v00, v01);
                *(float2*)&H[(size_t)(bm + r0 + 8) * Ff + bn + c] = make_float2(v10, v11);
            }
        }
    }
}

// --------------------------- down bf16 HMMA GEMM ---------------------------
// Block 128x128, 8 warps (2x4), warp tile 64x32.

__global__ void __launch_bounds__(256, 2) down_kernel(
        const __nv_bfloat16* __restrict__ Aq, const __nv_bfloat16* __restrict__ B,
        float* __restrict__ C, int N,
        const float* __restrict__ adq, const float* __restrict__ wdq) {
    extern __shared__ __align__(128) char smem[];
    const uint32_t sbase = smem_u32(smem);
    const int tid = threadIdx.x;
    const int lane = tid & 31;
    const int g = lane >> 2, tig = lane & 3;
    const int w = tid >> 5;
    const int wmb = (w >> 2) * 64;
    const int wnb = (w & 3) * 32;
    const int bm = blockIdx.y * 128, bn = blockIdx.x * 128;
    const size_t Kb = (size_t)Ff * 2;

    float acc[4][4][4];
#pragma unroll
    for (int mt = 0; mt < 4; mt++)
#pragma unroll
        for (int nt = 0; nt < 4; nt++)
#pragma unroll
            for (int k = 0; k < 4; k++) acc[mt][nt][k] = 0.0f;

    auto LOAD = [&](int kc, int s) {
        uint32_t sa = sbase + s * STG;
        const size_t kof = (size_t)kc * 128;
        const char* Ag = (const char*)Aq + (size_t)bm * Kb + kof;
        const char* Bg2 = (const char*)B + (size_t)bn * Kb + kof;
#pragma unroll
        for (int i = 0; i < 4; i++) {
            int idx = i * 256 + tid;
            int row = idx >> 3, ch = (idx & 7) * 16;
            cp16(sa + row * ROWB + ch, Ag + (size_t)row * Kb + ch);
        }
#pragma unroll
        for (int i = 0; i < 4; i++) {
            int idx = i * 256 + tid;
            int row = idx >> 3, ch = (idx & 7) * 16;
            cp16(sa + 18432 + row * ROWB + ch, Bg2 + (size_t)row * Kb + ch);
        }
        cp_commit();
    };

    const int NK = Ff / 64;   // 128
    LOAD(0, 0); LOAD(1, 1);

    const uint32_t a_row = (uint32_t)(lane & 15);
    const uint32_t a_k   = (uint32_t)((lane >> 4) * 16);
    const uint32_t b_row = (uint32_t)(((lane >> 4) << 3) + (lane & 7));
    const uint32_t b_k   = (uint32_t)(((lane >> 3) & 1) * 16);

    int cs = 0;
    for (int kc = 0; kc < NK; kc++) {
        cp_wait1();
        __syncthreads();
        int ls = cs + 2; if (ls >= 3) ls -= 3;
        if (kc + 2 < NK) LOAD(kc + 2, ls); else cp_commit();

        const uint32_t sa = sbase + cs * STG;
        const uint32_t sb = sa + 18432;
#pragma unroll
        for (int ks = 0; ks < 4; ks++) {
            uint32_t af[4][4], bf[4][2];
#pragma unroll
            for (int mt = 0; mt < 4; mt++)
                ldsm4(af[mt], sa + (uint32_t)(wmb + mt * 16 + a_row) * ROWB
                              + (uint32_t)(ks * 32) + a_k);
#pragma unroll
            for (int p = 0; p < 2; p++) {
                uint32_t t[4];
                ldsm4(t, sb + (uint32_t)(wnb + p * 16 + b_row) * ROWB
                         + (uint32_t)(ks * 32) + b_k);
                bf[2 * p][0] = t[0]; bf[2 * p][1] = t[1];
                bf[2 * p + 1][0] = t[2]; bf[2 * p + 1][1] = t[3];
            }
#pragma unroll
            for (int mt = 0; mt < 4; mt++)
#pragma unroll
                for (int nt = 0; nt < 4; nt++)
                    mma_bf16(acc[mt][nt], af[mt], bf[nt]);
        }
        cs++; if (cs == 3) cs = 0;
    }

    const float wsc = *wdq;
#pragma unroll
    for (int mt = 0; mt < 4; mt++) {
        const int r0 = bm + wmb + mt * 16 + g;
        const int r1 = r0 + 8;
        const float s0 = adq[r0] * wsc;
        const float s1 = adq[r1] * wsc;
#pragma unroll
        for (int nt = 0; nt < 4; nt++) {
            const int c = bn + wnb + nt * 8 + tig * 2;
            *(float2*)&C[(size_t)r0 * N + c] =
                make_float2(acc[mt][nt][0] * s0, acc[mt][nt][1] * s0);
            *(float2*)&C[(size_t)r1 * N + c] =
                make_float2(acc[mt][nt][2] * s1, acc[mt][nt][3] * s1);
        }
    }
}

// ------------------------------- launch ------------------------------------

extern "C" void kernel_launch(void* const* d_in, const int* in_sizes, int n_in,
                              void* d_out, int out_size) {
    const float* x  = (const float*)d_in[0];
    const float* wg = (const float*)d_in[1];
    const float* wu = (const float*)d_in[2];
    const float* wd = (const float*)d_in[3];
    float* out = (float*)d_out;

    __nv_bfloat16 *p_wgb, *p_wub, *p_wdb, *p_xb, *p_hb;
    float *p_H, *p_xdq, *p_hdq, *p_wdq;
    cudaGetSymbolAddress((void**)&p_wgb, g_wgb);
    cudaGetSymbolAddress((void**)&p_wub, g_wub);
    cudaGetSymbolAddress((void**)&p_wdb, g_wdb);
    cudaGetSymbolAddress((void**)&p_xb,  g_xb);
    cudaGetSymbolAddress((void**)&p_hb,  g_hb);
    cudaGetSymbolAddress((void**)&p_H,   g_H);
    cudaGetSymbolAddress((void**)&p_xdq, g_xdq);
    cudaGetSymbolAddress((void**)&p_hdq, g_hdq);
    cudaGetSymbolAddress((void**)&p_wdq, g_wdq);

    cudaFuncSetAttribute(gateup_kernel,
                         cudaFuncAttributeMaxDynamicSharedMemorySize, GEMM_SMEM);
    cudaFuncSetAttribute(down_kernel,
                         cudaFuncAttributeMaxDynamicSharedMemorySize, GEMM_SMEM);

    const int nW = Ff * Dd;
    const int nW4 = nW / 4;
    const double inv_n = 1.0 / (double)nW;

    // #1: x-quant (also zeroes g_wsum; weights untouched here)
    actquant_x_kernel<<<Mm / 8, 256>>>(x, p_xb, p_xdq);

    // #2-#5: gate / up weight absum -> wquant pairs (L2-paired)
    absum_kernel<<<2048, 256>>>(wg, nW4, 0);
    wquant_kernel<<<2048, 256>>>(wg, p_wgb, nW4, 0, inv_n);
    absum_kernel<<<2048, 256>>>(wu, nW4, 1);
    wquant_kernel<<<2048, 256>>>(wu, p_wub, nW4, 1, inv_n);

    // #6: fused gate+up GEMM (ncu -s 5 -c 1 captures this launch)
    gateup_kernel<<<dim3(Ff / 64, Mm / 128), 256, GEMM_SMEM>>>(
        p_xb, p_wgb, p_wub, p_H, p_xdq);

    // #7-#8: down-weight quant (independent of gateup; needed only by down)
    absum_kernel<<<2048, 256>>>(wd, nW4, 2);
    wquant_kernel<<<2048, 256>>>(wd, p_wdb, nW4, 2, inv_n);

    // #9: H quant
    actquant_h_kernel<<<Mm, 512>>>(p_H, p_hb, p_hdq);

    // #10: down -> d_out  [4096, 2048]
    down_kernel<<<dim3(Dd / 128, Mm / 128), 256, GEMM_SMEM>>>(
        p_hb, p_wdb, out, Dd, p_hdq, p_wdq + 2);
}

// round 17
// speedup vs baseline: 1.5802x; 1.0082x over previous
#include <cuda_runtime.h>
#include <cuda_bf16.h>
#include <math.h>
#include <stdint.h>

// ---------------------------------------------------------------------------
// BitNet b1.58 MLP, exact-integer formulation on legacy bf16 HMMA.
// R14 -> R15: fork-join multi-stream schedule inside graph capture.
// Weight quant pipelines (absum+wquant per tensor) run on side streams:
// gate/up pairs overlap actquant_x; the down pair overlaps gateup entirely.
// All kernels byte-identical to R13/R14. rel_err 5.449e-4 bit-identical.
// ---------------------------------------------------------------------------

#define Dd 2048
#define Ff 8192
#define Mm 4096

#define ROWB 144                 // 64 bf16 = 128B data + 16B pad
#define STG  36864               // 256 rows * 144B per pipeline stage
#define GEMM_SMEM (3 * STG)      // 110592 -> 2 CTAs/SM

__device__ __align__(128) __nv_bfloat16 g_wgb[Ff * Dd];
__device__ __align__(128) __nv_bfloat16 g_wub[Ff * Dd];
__device__ __align__(128) __nv_bfloat16 g_wdb[Dd * Ff];
__device__ __align__(128) __nv_bfloat16 g_xb[Mm * Dd];
__device__ __align__(128) __nv_bfloat16 g_hb[(size_t)Mm * Ff];
__device__ __align__(128) float g_H[(size_t)Mm * Ff];
__device__ float  g_xdq[Mm];
__device__ float  g_hdq[Mm];
__device__ double g_wsum[3];
__device__ float  g_wdq[3];

// ------------------------------ utilities ----------------------------------

__device__ __forceinline__ uint32_t smem_u32(const void* p) {
    uint32_t a;
    asm("{ .reg .u64 t; cvta.to.shared.u64 t, %1; cvt.u32.u64 %0, t; }"
        : "=r"(a) : "l"(p));
    return a;
}
__device__ __forceinline__ void cp16(uint32_t dst, const void* src) {
    asm volatile("cp.async.cg.shared.global [%0], [%1], 16;"
                 :: "r"(dst), "l"(src) : "memory");
}
__device__ __forceinline__ void cp_commit() {
    asm volatile("cp.async.commit_group;" ::: "memory");
}
__device__ __forceinline__ void cp_wait1() {
    asm volatile("cp.async.wait_group 1;" ::: "memory");
}
__device__ __forceinline__ void ldsm4(uint32_t* r, uint32_t addr) {
    asm volatile("ldmatrix.sync.aligned.m8n8.x4.shared.b16 {%0,%1,%2,%3}, [%4];"
                 : "=r"(r[0]), "=r"(r[1]), "=r"(r[2]), "=r"(r[3]) : "r"(addr));
}
__device__ __forceinline__ void mma_bf16(float* c, const uint32_t* a, const uint32_t* b) {
    asm volatile(
        "mma.sync.aligned.m16n8k16.row.col.f32.bf16.bf16.f32 "
        "{%0,%1,%2,%3}, {%4,%5,%6,%7}, {%8,%9}, {%0,%1,%2,%3};"
        : "+f"(c[0]), "+f"(c[1]), "+f"(c[2]), "+f"(c[3])
        : "r"(a[0]), "r"(a[1]), "r"(a[2]), "r"(a[3]), "r"(b[0]), "r"(b[1]));
}

__device__ __forceinline__ double warpReduceSumD(double v) {
#pragma unroll
    for (int o = 16; o > 0; o >>= 1) v += __shfl_xor_sync(0xffffffffu, v, o);
    return v;
}
__device__ __forceinline__ float warpReduceMax(float v) {
#pragma unroll
    for (int o = 16; o > 0; o >>= 1) v = fmaxf(v, __shfl_xor_sync(0xffffffffu, v, o));
    return v;
}
__device__ __forceinline__ float silu_f(float g) {
    float sig;
    if (g >= 0.0f) {
        sig = 1.0f / (1.0f + expf(-g));
    } else {
        float e = expf(g);
        sig = e / (1.0f + e);
    }
    return g * sig;
}

// ---------------------------- small kernels --------------------------------

__global__ void zero_scalars_kernel() {
    if (threadIdx.x < 3) g_wsum[threadIdx.x] = 0.0;
}

// sum |W| (one tensor): grid-stride, unroll-4 for MLP, fp32 partials -> double
__global__ void __launch_bounds__(256) absum_kernel(
        const float* __restrict__ W, int n4, int slot) {
    float s = 0.0f;
    const float4* W4 = (const float4*)W;
    const int stride = gridDim.x * blockDim.x;
#pragma unroll 4
    for (int i = blockIdx.x * blockDim.x + threadIdx.x; i < n4; i += stride) {
        float4 w = W4[i];
        s += (fabsf(w.x) + fabsf(w.y)) + (fabsf(w.z) + fabsf(w.w));
    }
    double d = warpReduceSumD((double)s);
    __shared__ double rs[8];
    int warp = threadIdx.x >> 5, lane = threadIdx.x & 31;
    if (lane == 0) rs[warp] = d;
    __syncthreads();
    if (threadIdx.x == 0) {
        double t = 0.0;
#pragma unroll
        for (int i = 0; i < 8; i++) t += rs[i];
        atomicAdd(&g_wsum[slot], t);
    }
}

// ternary weight quant (one tensor) -> bf16 {-1,0,1}; grid-stride, unroll-4
__global__ void __launch_bounds__(256) wquant_kernel(
        const float* __restrict__ W, __nv_bfloat16* __restrict__ Q,
        int n4, int slot, double inv_n) {
    float mean = fmaxf((float)(g_wsum[slot] * inv_n), 1e-5f);
    float ws = 1.0f / mean;
    const int stride = gridDim.x * blockDim.x;
#pragma unroll 4
    for (int i = blockIdx.x * blockDim.x + threadIdx.x; i < n4; i += stride) {
        float4 w = ((const float4*)W)[i];
        float qx = rintf(fminf(fmaxf(w.x * ws, -1.0f), 1.0f));
        float qy = rintf(fminf(fmaxf(w.y * ws, -1.0f), 1.0f));
        float qz = rintf(fminf(fmaxf(w.z * ws, -1.0f), 1.0f));
        float qw = rintf(fminf(fmaxf(w.w * ws, -1.0f), 1.0f));
        __nv_bfloat162 lo = __nv_bfloat162(__float2bfloat16(qx), __float2bfloat16(qy));
        __nv_bfloat162 hi = __nv_bfloat162(__float2bfloat16(qz), __float2bfloat16(qw));
        uint2 pk;
        pk.x = *(uint32_t*)&lo;
        pk.y = *(uint32_t*)&hi;
        ((uint2*)Q)[i] = pk;
    }
    if (blockIdx.x == 0 && threadIdx.x == 0) g_wdq[slot] = 1.0f / ws;
}

// warp-per-row rmsnorm+quant for D=2048 (row held in registers, no smem)
__global__ void __launch_bounds__(256) actquant_x_kernel(
        const float* __restrict__ A, __nv_bfloat16* __restrict__ Q,
        float* __restrict__ DQ) {
    const int lane = threadIdx.x & 31;
    const int row = blockIdx.x * 8 + (threadIdx.x >> 5);
    const float4* a4 = (const float4*)(A + (size_t)row * Dd);
    uint2* q2 = (uint2*)(Q + (size_t)row * Dd);

    float4 v[16];
    double ss = 0.0;
    float mx = 0.0f;
#pragma unroll
    for (int p = 0; p < 16; p++) {
        v[p] = a4[p * 32 + lane];
        float q = (v[p].x * v[p].x + v[p].y * v[p].y)
                + (v[p].z * v[p].z + v[p].w * v[p].w);
        ss += (double)q;
        mx = fmaxf(mx, fmaxf(fmaxf(fabsf(v[p].x), fabsf(v[p].y)),
                             fmaxf(fabsf(v[p].z), fabsf(v[p].w))));
    }
    ss = warpReduceSumD(ss);
    mx = warpReduceMax(mx);
    float mean = (float)(ss / (double)Dd);
    float c = rsqrtf(mean + 1e-6f);
    float m = fmaxf(c * mx, 1e-5f);
    float scale = 127.0f / m;
    if (lane == 0) DQ[row] = 1.0f / scale;
#pragma unroll
    for (int p = 0; p < 16; p++) {
        float c0 = rintf(fminf(fmaxf((c * v[p].x) * scale, -128.0f), 127.0f));
        float c1 = rintf(fminf(fmaxf((c * v[p].y) * scale, -128.0f), 127.0f));
        float c2 = rintf(fminf(fmaxf((c * v[p].z) * scale, -128.0f), 127.0f));
        float c3 = rintf(fminf(fmaxf((c * v[p].w) * scale, -128.0f), 127.0f));
        __nv_bfloat162 lo = __nv_bfloat162(__float2bfloat16(c0), __float2bfloat16(c1));
        __nv_bfloat162 hi = __nv_bfloat162(__float2bfloat16(c2), __float2bfloat16(c3));
        uint2 pk;
        pk.x = *(uint32_t*)&lo;
        pk.y = *(uint32_t*)&hi;
        q2[p * 32 + lane] = pk;
    }
}

// block-per-row rmsnorm+quant for F=8192 (512 threads, 16 floats/thread)
__global__ void __launch_bounds__(512) actquant_h_kernel(
        const float* __restrict__ A, __nv_bfloat16* __restrict__ Q,
        float* __restrict__ DQ) {
    __shared__ double rs[16];
    __shared__ float rm[16];
    __shared__ float s_c, s_scale;
    const int tid = threadIdx.x;
    const int row = blockIdx.x;
    const float4* a4 = (const float4*)(A + (size_t)row * Ff);
    uint2* q2 = (uint2*)(Q + (size_t)row * Ff);

    float4 v[4];
    double ss = 0.0;
    float mx = 0.0f;
#pragma unroll
    for (int p = 0; p < 4; p++) {
        v[p] = a4[p * 512 + tid];
        float q = (v[p].x * v[p].x + v[p].y * v[p].y)
                + (v[p].z * v[p].z + v[p].w * v[p].w);
        ss += (double)q;
        mx = fmaxf(mx, fmaxf(fmaxf(fabsf(v[p].x), fabsf(v[p].y)),
                             fmaxf(fabsf(v[p].z), fabsf(v[p].w))));
    }
    ss = warpReduceSumD(ss);
    mx = warpReduceMax(mx);
    int warp = tid >> 5, lane = tid & 31;
    if (lane == 0) { rs[warp] = ss; rm[warp] = mx; }
    __syncthreads();
    if (tid == 0) {
        double S = 0.0;
        float Mx = 0.0f;
#pragma unroll
        for (int i = 0; i < 16; i++) { S += rs[i]; Mx = fmaxf(Mx, rm[i]); }
        float mean = (float)(S / (double)Ff);
        float c = rsqrtf(mean + 1e-6f);
        float m = fmaxf(c * Mx, 1e-5f);
        float scale = 127.0f / m;
        s_c = c; s_scale = scale;
        DQ[row] = 1.0f / scale;
    }
    __syncthreads();
    const float c = s_c, scale = s_scale;
#pragma unroll
    for (int p = 0; p < 4; p++) {
        float c0 = rintf(fminf(fmaxf((c * v[p].x) * scale, -128.0f), 127.0f));
        float c1 = rintf(fminf(fmaxf((c * v[p].y) * scale, -128.0f), 127.0f));
        float c2 = rintf(fminf(fmaxf((c * v[p].z) * scale, -128.0f), 127.0f));
        float c3 = rintf(fminf(fmaxf((c * v[p].w) * scale, -128.0f), 127.0f));
        __nv_bfloat162 lo = __nv_bfloat162(__float2bfloat16(c0), __float2bfloat16(c1));
        __nv_bfloat162 hi = __nv_bfloat162(__float2bfloat16(c2), __float2bfloat16(c3));
        uint2 pk;
        pk.x = *(uint32_t*)&lo;
        pk.y = *(uint32_t*)&hi;
        q2[p * 512 + tid] = pk;
    }
}

// --------------------- fused gate+up bf16 HMMA GEMM ------------------------
// Single-buffered fragments, 64x32 warp tiles, 2 CTAs/SM.
// Epilogue: gate warps stage silu(g) in smem; up warps multiply, write H.

__global__ void __launch_bounds__(256, 2) gateup_kernel(
        const __nv_bfloat16* __restrict__ Aq,
        const __nv_bfloat16* __restrict__ Bg,
        const __nv_bfloat16* __restrict__ Bu,
        float* __restrict__ H,
        const float* __restrict__ adq) {
    extern __shared__ __align__(128) char smem[];
    const uint32_t sbase = smem_u32(smem);
    const int tid = threadIdx.x;
    const int lane = tid & 31;
    const int g = lane >> 2, tig = lane & 3;
    const int w = tid >> 5;
    const int uw = w & 3;
    const int isUp = w >> 2;
    const int wmb = (uw >> 1) * 64;
    const int wnb = (uw & 1) * 32;
    const int bm = blockIdx.y * 128, bn = blockIdx.x * 64;
    const size_t Kb = (size_t)Dd * 2;

    float acc[4][4][4];
#pragma unroll
    for (int mt = 0; mt < 4; mt++)
#pragma unroll
        for (int nt = 0; nt < 4; nt++)
#pragma unroll
            for (int k = 0; k < 4; k++) acc[mt][nt][k] = 0.0f;

    auto LOAD = [&](int kc, int s) {
        uint32_t sa = sbase + s * STG;
        const size_t kof = (size_t)kc * 128;
        const char* Ag = (const char*)Aq + (size_t)bm * Kb + kof;
        const char* Gg = (const char*)Bg + (size_t)bn * Kb + kof;
        const char* Ug = (const char*)Bu + (size_t)bn * Kb + kof;
#pragma unroll
        for (int i = 0; i < 4; i++) {
            int idx = i * 256 + tid;
            int row = idx >> 3, ch = (idx & 7) * 16;
            cp16(sa + row * ROWB + ch, Ag + (size_t)row * Kb + ch);
        }
#pragma unroll
        for (int i = 0; i < 2; i++) {
            int idx = i * 256 + tid;
            int row = idx >> 3, ch = (idx & 7) * 16;
            cp16(sa + 18432 + row * ROWB + ch, Gg + (size_t)row * Kb + ch);
        }
#pragma unroll
        for (int i = 0; i < 2; i++) {
            int idx = i * 256 + tid;
            int row = idx >> 3, ch = (idx & 7) * 16;
            cp16(sa + 27648 + row * ROWB + ch, Ug + (size_t)row * Kb + ch);
        }
        cp_commit();
    };

    const int NK = Dd / 64;   // 32
    LOAD(0, 0); LOAD(1, 1);

    const uint32_t a_row = (uint32_t)(lane & 15);
    const uint32_t a_k   = (uint32_t)((lane >> 4) * 16);
    const uint32_t b_row = (uint32_t)(((lane >> 4) << 3) + (lane & 7));
    const uint32_t b_k   = (uint32_t)(((lane >> 3) & 1) * 16);

    int cs = 0;
    for (int kc = 0; kc < NK; kc++) {
        cp_wait1();
        __syncthreads();
        int ls = cs + 2; if (ls >= 3) ls -= 3;
        if (kc + 2 < NK) LOAD(kc + 2, ls); else cp_commit();

        const uint32_t sa = sbase + cs * STG;
        const uint32_t sbW = sa + 18432 + (uint32_t)isUp * 9216;
#pragma unroll
        for (int ks = 0; ks < 4; ks++) {
            uint32_t af[4][4], bf[4][2];
#pragma unroll
            for (int mt = 0; mt < 4; mt++)
                ldsm4(af[mt], sa + (uint32_t)(wmb + mt * 16 + a_row) * ROWB
                              + (uint32_t)(ks * 32) + a_k);
#pragma unroll
            for (int p = 0; p < 2; p++) {
                uint32_t t[4];
                ldsm4(t, sbW + (uint32_t)(wnb + p * 16 + b_row) * ROWB
                         + (uint32_t)(ks * 32) + b_k);
                bf[2 * p][0] = t[0]; bf[2 * p][1] = t[1];
                bf[2 * p + 1][0] = t[2]; bf[2 * p + 1][1] = t[3];
            }
#pragma unroll
            for (int mt = 0; mt < 4; mt++)
#pragma unroll
                for (int nt = 0; nt < 4; nt++)
                    mma_bf16(acc[mt][nt], af[mt], bf[nt]);
        }
        cs++; if (cs == 3) cs = 0;
    }

    // ---- epilogue: exchange silu(g) via smem, write H = silu(g)*u ----
    __syncthreads();
    float* hstage = (float*)smem;    // [128][68]
    if (!isUp) {
        const float wgs = g_wdq[0];
#pragma unroll
        for (int mt = 0; mt < 4; mt++) {
            int r0 = wmb + mt * 16 + g;
            float s0 = adq[bm + r0] * wgs;
            float s1 = adq[bm + r0 + 8] * wgs;
#pragma unroll
            for (int nt = 0; nt < 4; nt++) {
                int c = wnb + nt * 8 + tig * 2;
                hstage[r0 * 68 + c]           = silu_f(acc[mt][nt][0] * s0);
                hstage[r0 * 68 + c + 1]       = silu_f(acc[mt][nt][1] * s0);
                hstage[(r0 + 8) * 68 + c]     = silu_f(acc[mt][nt][2] * s1);
                hstage[(r0 + 8) * 68 + c + 1] = silu_f(acc[mt][nt][3] * s1);
            }
        }
    }
    __syncthreads();
    if (isUp) {
        const float wus = g_wdq[1];
#pragma unroll
        for (int mt = 0; mt < 4; mt++) {
            int r0 = wmb + mt * 16 + g;
            float s0 = adq[bm + r0] * wus;
            float s1 = adq[bm + r0 + 8] * wus;
#pragma unroll
            for (int nt = 0; nt < 4; nt++) {
                int c = wnb + nt * 8 + tig * 2;
                float v00 = acc[mt][nt][0] * s0 * hstage[r0 * 68 + c];
                float v01 = acc[mt][nt][1] * s0 * hstage[r0 * 68 + c + 1];
                float v10 = acc[mt][nt][2] * s1 * hstage[(r0 + 8) * 68 + c];
                float v11 = acc[mt][nt][3] * s1 * hstage[(r0 + 8) * 68 + c + 1];
                *(float2*)&H[(size_t)(bm + r0) * Ff + bn + c] = make_float2(v00, v01);
                *(float2*)&H[(size_t)(bm + r0 + 8) * Ff + bn + c] = make_float2(v10, v11);
            }
        }
    }
}

// --------------------------- down bf16 HMMA GEMM ---------------------------
// Block 128x128, 8 warps (2x4), warp tile 64x32.

__global__ void __launch_bounds__(256, 2) down_kernel(
        const __nv_bfloat16* __restrict__ Aq, const __nv_bfloat16* __restrict__ B,
        float* __restrict__ C, int N,
        const float* __restrict__ adq, const float* __restrict__ wdq) {
    extern __shared__ __align__(128) char smem[];
    const uint32_t sbase = smem_u32(smem);
    const int tid = threadIdx.x;
    const int lane = tid & 31;
    const int g = lane >> 2, tig = lane & 3;
    const int w = tid >> 5;
    const int wmb = (w >> 2) * 64;
    const int wnb = (w & 3) * 32;
    const int bm = blockIdx.y * 128, bn = blockIdx.x * 128;
    const size_t Kb = (size_t)Ff * 2;

    float acc[4][4][4];
#pragma unroll
    for (int mt = 0; mt < 4; mt++)
#pragma unroll
        for (int nt = 0; nt < 4; nt++)
#pragma unroll
            for (int k = 0; k < 4; k++) acc[mt][nt][k] = 0.0f;

    auto LOAD = [&](int kc, int s) {
        uint32_t sa = sbase + s * STG;
        const size_t kof = (size_t)kc * 128;
        const char* Ag = (const char*)Aq + (size_t)bm * Kb + kof;
        const char* Bg2 = (const char*)B + (size_t)bn * Kb + kof;
#pragma unroll
        for (int i = 0; i < 4; i++) {
            int idx = i * 256 + tid;
            int row = idx >> 3, ch = (idx & 7) * 16;
            cp16(sa + row * ROWB + ch, Ag + (size_t)row * Kb + ch);
        }
#pragma unroll
        for (int i = 0; i < 4; i++) {
            int idx = i * 256 + tid;
            int row = idx >> 3, ch = (idx & 7) * 16;
            cp16(sa + 18432 + row * ROWB + ch, Bg2 + (size_t)row * Kb + ch);
        }
        cp_commit();
    };

    const int NK = Ff / 64;   // 128
    LOAD(0, 0); LOAD(1, 1);

    const uint32_t a_row = (uint32_t)(lane & 15);
    const uint32_t a_k   = (uint32_t)((lane >> 4) * 16);
    const uint32_t b_row = (uint32_t)(((lane >> 4) << 3) + (lane & 7));
    const uint32_t b_k   = (uint32_t)(((lane >> 3) & 1) * 16);

    int cs = 0;
    for (int kc = 0; kc < NK; kc++) {
        cp_wait1();
        __syncthreads();
        int ls = cs + 2; if (ls >= 3) ls -= 3;
        if (kc + 2 < NK) LOAD(kc + 2, ls); else cp_commit();

        const uint32_t sa = sbase + cs * STG;
        const uint32_t sb = sa + 18432;
#pragma unroll
        for (int ks = 0; ks < 4; ks++) {
            uint32_t af[4][4], bf[4][2];
#pragma unroll
            for (int mt = 0; mt < 4; mt++)
                ldsm4(af[mt], sa + (uint32_t)(wmb + mt * 16 + a_row) * ROWB
                              + (uint32_t)(ks * 32) + a_k);
#pragma unroll
            for (int p = 0; p < 2; p++) {
                uint32_t t[4];
                ldsm4(t, sb + (uint32_t)(wnb + p * 16 + b_row) * ROWB
                         + (uint32_t)(ks * 32) + b_k);
                bf[2 * p][0] = t[0]; bf[2 * p][1] = t[1];
                bf[2 * p + 1][0] = t[2]; bf[2 * p + 1][1] = t[3];
            }
#pragma unroll
            for (int mt = 0; mt < 4; mt++)
#pragma unroll
                for (int nt = 0; nt < 4; nt++)
                    mma_bf16(acc[mt][nt], af[mt], bf[nt]);
        }
        cs++; if (cs == 3) cs = 0;
    }

    const float wsc = *wdq;
#pragma unroll
    for (int mt = 0; mt < 4; mt++) {
        const int r0 = bm + wmb + mt * 16 + g;
        const int r1 = r0 + 8;
        const float s0 = adq[r0] * wsc;
        const float s1 = adq[r1] * wsc;
#pragma unroll
        for (int nt = 0; nt < 4; nt++) {
            const int c = bn + wnb + nt * 8 + tig * 2;
            *(float2*)&C[(size_t)r0 * N + c] =
                make_float2(acc[mt][nt][0] * s0, acc[mt][nt][1] * s0);
            *(float2*)&C[(size_t)r1 * N + c] =
                make_float2(acc[mt][nt][2] * s1, acc[mt][nt][3] * s1);
        }
    }
}

// ------------------------------- launch ------------------------------------

extern "C" void kernel_launch(void* const* d_in, const int* in_sizes, int n_in,
                              void* d_out, int out_size) {
    const float* x  = (const float*)d_in[0];
    const float* wg = (const float*)d_in[1];
    const float* wu = (const float*)d_in[2];
    const float* wd = (const float*)d_in[3];
    float* out = (float*)d_out;

    __nv_bfloat16 *p_wgb, *p_wub, *p_wdb, *p_xb, *p_hb;
    float *p_H, *p_xdq, *p_hdq, *p_wdq;
    cudaGetSymbolAddress((void**)&p_wgb, g_wgb);
    cudaGetSymbolAddress((void**)&p_wub, g_wub);
    cudaGetSymbolAddress((void**)&p_wdb, g_wdb);
    cudaGetSymbolAddress((void**)&p_xb,  g_xb);
    cudaGetSymbolAddress((void**)&p_hb,  g_hb);
    cudaGetSymbolAddress((void**)&p_H,   g_H);
    cudaGetSymbolAddress((void**)&p_xdq, g_xdq);
    cudaGetSymbolAddress((void**)&p_hdq, g_hdq);
    cudaGetSymbolAddress((void**)&p_wdq, g_wdq);

    // One-time setup on the (uncaptured) correctness call: streams, events,
    // smem attrs. No device allocations involved.
    static cudaStream_t s1 = nullptr, s2 = nullptr, s3 = nullptr;
    static cudaEvent_t eFork = nullptr, e1 = nullptr, e2 = nullptr, e3 = nullptr;
    if (s1 == nullptr) {
        cudaStreamCreateWithFlags(&s1, cudaStreamNonBlocking);
        cudaStreamCreateWithFlags(&s2, cudaStreamNonBlocking);
        cudaStreamCreateWithFlags(&s3, cudaStreamNonBlocking);
        cudaEventCreateWithFlags(&eFork, cudaEventDisableTiming);
        cudaEventCreateWithFlags(&e1, cudaEventDisableTiming);
        cudaEventCreateWithFlags(&e2, cudaEventDisableTiming);
        cudaEventCreateWithFlags(&e3, cudaEventDisableTiming);
        cudaFuncSetAttribute(gateup_kernel,
                             cudaFuncAttributeMaxDynamicSharedMemorySize, GEMM_SMEM);
        cudaFuncSetAttribute(down_kernel,
                             cudaFuncAttributeMaxDynamicSharedMemorySize, GEMM_SMEM);
    }

    const int nW = Ff * Dd;
    const int nW4 = nW / 4;
    const double inv_n = 1.0 / (double)nW;

    // main stream: zero accumulators, then fork
    zero_scalars_kernel<<<1, 32>>>();
    cudaEventRecord(eFork, 0);
    cudaStreamWaitEvent(s1, eFork, 0);
    cudaStreamWaitEvent(s2, eFork, 0);
    cudaStreamWaitEvent(s3, eFork, 0);

    // main: x-quant (overlaps weight quant below)
    actquant_x_kernel<<<Mm / 8, 256>>>(x, p_xb, p_xdq);

    // s1/s2: gate and up weight quant pipelines (concurrent)
    absum_kernel<<<2048, 256, 0, s1>>>(wg, nW4, 0);
    wquant_kernel<<<2048, 256, 0, s1>>>(wg, p_wgb, nW4, 0, inv_n);
    cudaEventRecord(e1, s1);

    absum_kernel<<<2048, 256, 0, s2>>>(wu, nW4, 1);
    wquant_kernel<<<2048, 256, 0, s2>>>(wu, p_wub, nW4, 1, inv_n);
    cudaEventRecord(e2, s2);

    // s3: down weight quant pipeline (overlaps gateup below)
    absum_kernel<<<2048, 256, 0, s3>>>(wd, nW4, 2);
    wquant_kernel<<<2048, 256, 0, s3>>>(wd, p_wdb, nW4, 2, inv_n);
    cudaEventRecord(e3, s3);

    // join gate/up quant into main, run fused gate+up GEMM
    cudaStreamWaitEvent(0, e1, 0);
    cudaStreamWaitEvent(0, e2, 0);
    gateup_kernel<<<dim3(Ff / 64, Mm / 128), 256, GEMM_SMEM>>>(
        p_xb, p_wgb, p_wub, p_H, p_xdq);

    // H quant on main
    actquant_h_kernel<<<Mm, 512>>>(p_H, p_hb, p_hdq);

    // join down-weight quant, run down GEMM -> d_out
    cudaStreamWaitEvent(0, e3, 0);
    down_kernel<<<dim3(Dd / 128, Mm / 128), 256, GEMM_SMEM>>>(
        p_hb, p_wdb, out, Dd, p_hdq, p_wdq + 2);
}